// round 14
// baseline (speedup 1.0000x reference)
#include <cuda_runtime.h>
#include <math.h>
#include <stdint.h>

#define NEG_INF   (-3.402823466e38f)
#define SUPPRESS  (-1e10f)
#define VALID_THR (-1e9f)
#define BBOX_CLIP 4.135166556742356f

// level tables
__device__ __constant__ int c_S[5]      = {128, 64, 32, 16, 8};
__device__ __constant__ int c_cumB[6]   = {0, 2048, 2560, 2688, 2720, 2728};          // conv blocks (16 px/blk)
__device__ __constant__ int c_Poff[6]   = {0, 32768, 40960, 43008, 43520, 43648};     // pixel base (both b)
__device__ __constant__ int c_Aoff[6]   = {0, 49152, 61440, 64512, 65280, 65472};     // anchor base per b
__device__ __constant__ int c_nl[5]     = {49152, 12288, 3072, 768, 192};
__device__ __constant__ int c_kl[5]     = {400, 400, 400, 400, 192};

// ---------------- scratch ----------------
__device__ float g_hfeat[43648 * 256];           // all-level conv output (pixel-major)
__device__ float g_raw[43648 * 16];              // per-pixel 15 head outputs (padded 16)
__device__ float g_scores[2 * 65472];
__device__ float g_boxes[2 * 65472 * 4];
__device__ float g_ts[2 * 5 * 400];
__device__ float g_tb[2 * 5 * 400 * 4];
__device__ int   g_ti[2 * 5 * 400];
__device__ float g_cs[2 * 640];
__device__ float g_cb[2 * 640 * 4];
__device__ float g_rois[2 * 512 * 4];
__device__ float g_dummy_s[2 * 512];
__device__ int   g_dummy_i[2 * 512];
__device__ float g_x[2 * 512 * 12544];
__device__ float g_h1[2 * 512 * 1024];
__device__ float g_h2[2 * 512 * 1024];
__device__ float g_cls[2 * 512 * 91];
__device__ float g_boxr[2 * 512 * 364];
__device__ float g_sc[2 * 46080];
__device__ float g_bx[2 * 46080 * 4];
__device__ float g_dts[2 * 500];
__device__ float g_dtb[2 * 500 * 4];
__device__ int   g_dti[2 * 500];

__device__ __forceinline__ float iou_f(float ay1, float ax1, float ay2, float ax2,
                                       float by1, float bx1, float by2, float bx2) {
    float areaA = fmaxf(ay2 - ay1, 0.f) * fmaxf(ax2 - ax1, 0.f);
    float areaB = fmaxf(by2 - by1, 0.f) * fmaxf(bx2 - bx1, 0.f);
    float iy1 = fmaxf(ay1, by1), ix1 = fmaxf(ax1, bx1);
    float iy2 = fminf(ay2, by2), ix2 = fminf(ax2, bx2);
    float inter = fmaxf(iy2 - iy1, 0.f) * fmaxf(ix2 - ix1, 0.f);
    return inter / (areaA + areaB - inter + 1e-8f);
}

__device__ __forceinline__ unsigned int flip_f(float f) {
    unsigned int u = __float_as_uint(f);
    return u ^ ((u & 0x80000000u) ? 0xFFFFFFFFu : 0x80000000u);
}

// ---------------- batched RPN 3x3 conv + relu (16 px/block, 64 threads, 4 co/thread) ----------------
// per-accumulator FMA order (kh, kw, ci ascending) identical to R13 -> bitwise same.
__global__ void conv3x3_relu_kernel(const float* __restrict__ f2, const float* __restrict__ f3,
                                    const float* __restrict__ f4, const float* __restrict__ f5,
                                    const float* __restrict__ f6,
                                    const float* __restrict__ w, const float* __restrict__ bias) {
    int bid = blockIdx.x;
    int lvl = 0;
#pragma unroll
    for (int l = 1; l < 5; l++) if (bid >= c_cumB[l]) lvl = l;
    int S = c_S[lvl];
    int local = bid - c_cumB[lvl];
    int xt_count = S >> 3;
    int yt_count = S >> 1;
    int b = local / (xt_count * yt_count);
    int rem = local % (xt_count * yt_count);
    int y0 = (rem / xt_count) * 2;
    int xt = (rem % xt_count) * 8;
    const float* in = (lvl == 0) ? f2 : (lvl == 1) ? f3 : (lvl == 2) ? f4 : (lvl == 3) ? f5 : f6;

    int co = threadIdx.x;                        // 0..63 ; owns co + 64*q, q=0..3
    __shared__ float4 s4buf[4 * 10 * 64];        // 40 KB
    float* sIn = (float*)s4buf;
    for (int idx = threadIdx.x; idx < 4 * 10 * 64; idx += 64) {
        int c4 = idx & 63;
        int xx = (idx >> 6) % 10;
        int r = idx / (10 * 64);
        int yy = y0 - 1 + r;
        int gx = xt - 1 + xx;
        float4 v = make_float4(0.f, 0.f, 0.f, 0.f);
        if (yy >= 0 && yy < S && gx >= 0 && gx < S)
            v = ((const float4*)(in + (((size_t)b * S + yy) * S + gx) * 256))[c4];
        s4buf[idx] = v;
    }
    __syncthreads();

    float acc[4][16];
#pragma unroll
    for (int q = 0; q < 4; q++) {
        float bq = bias[co + 64 * q];
#pragma unroll
        for (int p = 0; p < 16; p++) acc[q][p] = bq;
    }

    for (int kh = 0; kh < 3; kh++) {
        for (int kw = 0; kw < 3; kw++) {
            const float* wp = w + ((kh * 3 + kw) * 256) * 256 + co;
            for (int ci = 0; ci < 256; ci += 4) {
                float wv[4][4];
#pragma unroll
                for (int q = 0; q < 4; q++) {
#pragma unroll
                    for (int d = 0; d < 4; d++)
                        wv[q][d] = __ldg(wp + (ci + d) * 256 + 64 * q);
                }
#pragma unroll
                for (int p = 0; p < 16; p++) {
                    int py = p >> 3, px = p & 7;
                    float4 sv = *(const float4*)&sIn[((py + kh) * 10 + (px + kw)) * 256 + ci];
#pragma unroll
                    for (int q = 0; q < 4; q++) {
                        acc[q][p] = fmaf(sv.x, wv[q][0], acc[q][p]);
                        acc[q][p] = fmaf(sv.y, wv[q][1], acc[q][p]);
                        acc[q][p] = fmaf(sv.z, wv[q][2], acc[q][p]);
                        acc[q][p] = fmaf(sv.w, wv[q][3], acc[q][p]);
                    }
                }
            }
        }
    }
#pragma unroll
    for (int p = 0; p < 16; p++) {
        int py = p >> 3, px = p & 7;
        size_t pixel = (size_t)c_Poff[lvl] + ((size_t)b * S + (y0 + py)) * S + (xt + px);
#pragma unroll
        for (int q = 0; q < 4; q++)
            g_hfeat[pixel * 256 + co + 64 * q] = fmaxf(acc[q][p], 0.f);
    }
}

// ---------------- RPN 1x1 heads: 16 pixels/block, features staged once in smem ----------------
__global__ void rpn_head_kernel(const float* __restrict__ cw, const float* __restrict__ cb,
                                const float* __restrict__ bw, const float* __restrict__ bb) {
    __shared__ float sf[16 * 260];
    int p0 = blockIdx.x * 16;
    int tid = threadIdx.x;                       // 256

    for (int i = tid; i < 16 * 64; i += 256) {
        int row = i >> 6, c4 = i & 63;
        float4 v = ((const float4*)(g_hfeat + (size_t)(p0 + row) * 256))[c4];
        *(float4*)&sf[row * 260 + c4 * 4] = v;
    }
    __syncthreads();

    int p_local = tid >> 4;
    int o = tid & 15;
    if (o < 15) {
        float a;
        const float* wv;
        int st;
        if (o < 3) { a = cb[o]; wv = cw + o; st = 3; }
        else       { a = bb[o - 3]; wv = bw + (o - 3); st = 12; }
        const float* fp = sf + p_local * 260;
        for (int ci = 0; ci < 256; ci++) a += fp[ci] * __ldg(wv + ci * st);
        g_raw[(size_t)(p0 + p_local) * 16 + o] = a;
    }
}

// ---------------- RPN decode over all anchors ----------------
__global__ void rpn_decode_kernel(const float* __restrict__ info) {
    int t = blockIdx.x * blockDim.x + threadIdx.x;
    if (t >= 2 * 65472) return;
    int b = t / 65472;
    int r = t % 65472;
    int lvl = 0;
#pragma unroll
    for (int l = 1; l < 5; l++) if (r >= c_Aoff[l]) lvl = l;
    int local = r - c_Aoff[lvl];
    int hw = local / 3;
    int a = local % 3;
    int S = c_S[lvl];
    size_t p = (size_t)c_Poff[lvl] + (size_t)b * S * S + hw;

    const float* rp = g_raw + p * 16;
    float logit = rp[a];
    float d0 = rp[3 + a * 4 + 0], d1 = rp[3 + a * 4 + 1];
    float d2 = rp[3 + a * 4 + 2], d3 = rp[3 + a * 4 + 3];

    float score = 1.f / (1.f + expf(-logit));

    int stride = 4 << lvl;
    int iy = hw / S, ix = hw % S;
    const double AY[3] = {1.0, 1.4, 0.7};
    const double AX[3] = {1.0, 0.7, 1.4};
    double cyd = (iy + 0.5) * (double)stride;
    double cxd = (ix + 0.5) * (double)stride;
    double hd = 8.0 * (double)stride * AY[a];
    double wd = 8.0 * (double)stride * AX[a];
    float ay1 = (float)(cyd - hd / 2), ax1 = (float)(cxd - wd / 2);
    float ay2 = (float)(cyd + hd / 2), ax2 = (float)(cxd + wd / 2);

    float ah = ay2 - ay1, aw = ax2 - ax1;
    float acy = ay1 + 0.5f * ah, acx = ax1 + 0.5f * aw;

    float dh = fminf(d2, BBOX_CLIP), dw = fminf(d3, BBOX_CLIP);
    float ncy = d0 * ah + acy;
    float ncx = d1 * aw + acx;
    float nh = expf(dh) * ah;
    float nw = expf(dw) * aw;
    float y1 = ncy - 0.5f * nh, x1 = ncx - 0.5f * nw;
    float y2 = ncy + 0.5f * nh, x2 = ncx + 0.5f * nw;

    float ih = info[b * 5 + 0], iw = info[b * 5 + 1];
    y1 = fminf(fmaxf(y1, 0.f), ih);
    x1 = fminf(fmaxf(x1, 0.f), iw);
    y2 = fminf(fmaxf(y2, 0.f), ih);
    x2 = fminf(fmaxf(x2, 0.f), iw);

    int idx = b * 65472 + r;
    g_scores[idx] = score;
    g_boxes[idx * 4 + 0] = y1;
    g_boxes[idx * 4 + 1] = x1;
    g_boxes[idx * 4 + 2] = y2;
    g_boxes[idx * 4 + 3] = x2;
}

// ---------------- exact top-k via 64-bit radix select + bitonic sort ----------------
__global__ void topk_radix_kernel(int mode) {
    int tid = threadIdx.x;  // 1024
    const float* sc;
    const float* bxp;
    float* os;
    float* ob;
    int* oi;
    int n, k;
    if (mode == 0) {
        int b = blockIdx.x / 5, lvl = blockIdx.x % 5;
        sc = g_scores + b * 65472 + c_Aoff[lvl];
        bxp = g_boxes + (size_t)(b * 65472 + c_Aoff[lvl]) * 4;
        os = g_ts + (b * 5 + lvl) * 400;
        ob = g_tb + (size_t)(b * 5 + lvl) * 1600;
        oi = g_ti + (b * 5 + lvl) * 400;
        n = c_nl[lvl];
        k = c_kl[lvl];
    } else if (mode == 1) {
        int b = blockIdx.x;
        sc = g_cs + b * 640;
        bxp = g_cb + (size_t)b * 2560;
        os = g_dummy_s + b * 512;
        ob = g_rois + (size_t)b * 2048;
        oi = g_dummy_i + b * 512;
        n = 640; k = 512;
    } else {
        int b = blockIdx.x;
        sc = g_sc + b * 46080;
        bxp = g_bx + (size_t)b * 46080 * 4;
        os = g_dts + b * 500;
        ob = g_dtb + (size_t)b * 2000;
        oi = g_dti + b * 500;
        n = 46080; k = 500;
    }

    __shared__ unsigned int hist[256];
    __shared__ unsigned int suffix[256];
    __shared__ int s_krem, s_krem_next, s_chosen;
    __shared__ unsigned long long skeys[512];
    __shared__ int s_cnt;

    if (tid == 0) { s_krem = k; s_cnt = 0; }
    __syncthreads();

    unsigned long long pref = 0;
    for (int p = 7; p >= 0; p--) {
        if (tid < 256) hist[tid] = 0;
        __syncthreads();
        for (int j = tid; j < n; j += 1024) {
            unsigned long long key = (((unsigned long long)flip_f(sc[j])) << 32) | (unsigned int)(~(unsigned int)j);
            bool okc = (p == 7) || ((key >> (((unsigned)p + 1u) * 8u)) == pref);
            if (okc) atomicAdd(&hist[(unsigned)(key >> ((unsigned)p * 8u)) & 255u], 1u);
        }
        __syncthreads();
        if (tid < 256) suffix[tid] = hist[tid];
        __syncthreads();
        for (int d = 1; d < 256; d <<= 1) {
            unsigned v = 0;
            if (tid < 256) v = suffix[tid] + ((tid + d < 256) ? suffix[tid + d] : 0u);
            __syncthreads();
            if (tid < 256) suffix[tid] = v;
            __syncthreads();
        }
        if (tid < 256) {
            unsigned above = (tid == 255) ? 0u : suffix[tid + 1];
            if (suffix[tid] >= (unsigned)s_krem && above < (unsigned)s_krem) {
                s_chosen = tid;
                s_krem_next = s_krem - (int)above;
            }
        }
        __syncthreads();
        pref = (pref << 8) | (unsigned)s_chosen;
        if (tid == 0) s_krem = s_krem_next;
        __syncthreads();
    }
    unsigned long long kth = pref;

    for (int j = tid; j < n; j += 1024) {
        unsigned long long key = (((unsigned long long)flip_f(sc[j])) << 32) | (unsigned int)(~(unsigned int)j);
        if (key >= kth) skeys[atomicAdd(&s_cnt, 1)] = key;
    }
    __syncthreads();
    for (int idx = tid; idx < 512; idx += 1024)
        if (idx >= k) skeys[idx] = 0ull;
    __syncthreads();

    for (int size = 2; size <= 512; size <<= 1) {
        for (int stride = size >> 1; stride; stride >>= 1) {
            for (int idx = tid; idx < 512; idx += 1024) {
                int partner = idx ^ stride;
                if (partner > idx) {
                    bool dirDesc = ((idx & size) == 0);
                    unsigned long long a = skeys[idx], c2 = skeys[partner];
                    bool sw = dirDesc ? (a < c2) : (a > c2);
                    if (sw) { skeys[idx] = c2; skeys[partner] = a; }
                }
            }
            __syncthreads();
        }
    }

    for (int it = tid; it < k; it += 1024) {
        unsigned long long key = skeys[it];
        int j = (int)(~(unsigned int)(key & 0xFFFFFFFFull));
        os[it] = sc[j];
        oi[it] = j;
        ob[it * 4 + 0] = bxp[j * 4 + 0];
        ob[it * 4 + 1] = bxp[j * 4 + 1];
        ob[it * 4 + 2] = bxp[j * 4 + 2];
        ob[it * 4 + 3] = bxp[j * 4 + 3];
    }
}

// ---------------- batched RPN NMS (grid 10, 256 threads) ----------------
__global__ void nms_rpn_kernel() {
    int task = blockIdx.x;
    int b = task / 5, lvl = task % 5;
    int n = c_kl[lvl];
    int tid = threadIdx.x;  // 256
    __shared__ float sb[400 * 4];
    __shared__ float ss[400];
    __shared__ int sidx[128];
    __shared__ unsigned char sval[128];
    __shared__ float rv[8];
    __shared__ int ri[8];

    const float* tsg = g_ts + (b * 5 + lvl) * 400;
    const float* tbg = g_tb + (size_t)(b * 5 + lvl) * 1600;

    for (int j = tid; j < n; j += 256) {
        ss[j] = tsg[j];
        sb[j * 4 + 0] = tbg[j * 4 + 0];
        sb[j * 4 + 1] = tbg[j * 4 + 1];
        sb[j * 4 + 2] = tbg[j * 4 + 2];
        sb[j * 4 + 3] = tbg[j * 4 + 3];
    }
    __syncthreads();

    for (int it = 0; it < 128; it++) {
        float bv = NEG_INF;
        int bi = 0x7FFFFFFF;
        for (int j = tid; j < n; j += 256) {
            float v = ss[j];
            if (v > bv) { bv = v; bi = j; }
        }
#pragma unroll
        for (int o = 16; o; o >>= 1) {
            float ov = __shfl_down_sync(0xFFFFFFFFu, bv, o);
            int oidx = __shfl_down_sync(0xFFFFFFFFu, bi, o);
            if (ov > bv || (ov == bv && oidx < bi)) { bv = ov; bi = oidx; }
        }
        if ((tid & 31) == 0) { rv[tid >> 5] = bv; ri[tid >> 5] = bi; }
        __syncthreads();
        if (tid < 32) {
            bv = (tid < 8) ? rv[tid] : NEG_INF;
            bi = (tid < 8) ? ri[tid] : 0x7FFFFFFF;
#pragma unroll
            for (int o = 4; o; o >>= 1) {
                float ov = __shfl_down_sync(0xFFFFFFFFu, bv, o);
                int oidx = __shfl_down_sync(0xFFFFFFFFu, bi, o);
                if (ov > bv || (ov == bv && oidx < bi)) { bv = ov; bi = oidx; }
            }
            if (tid == 0) { rv[0] = bv; ri[0] = bi; }
        }
        __syncthreads();
        int j = ri[0];
        float vj = rv[0];
        if (tid == 0) { sidx[it] = j; sval[it] = (vj > VALID_THR) ? 1 : 0; }
        float jy1 = sb[j * 4 + 0], jx1 = sb[j * 4 + 1];
        float jy2 = sb[j * 4 + 2], jx2 = sb[j * 4 + 3];
        __syncthreads();
        for (int t = tid; t < n; t += 256) {
            float u = iou_f(jy1, jx1, jy2, jx2,
                            sb[t * 4 + 0], sb[t * 4 + 1], sb[t * 4 + 2], sb[t * 4 + 3]);
            if (u >= 0.7f) ss[t] = SUPPRESS;
        }
        __syncthreads();
    }

    for (int i = tid; i < 128; i += 256) {
        int j = sidx[i];
        bool ok = sval[i] != 0;
        int oidx = b * 640 + lvl * 128 + i;
        g_cs[oidx] = ok ? tsg[j] : SUPPRESS;
        g_cb[oidx * 4 + 0] = ok ? tbg[j * 4 + 0] : 0.f;
        g_cb[oidx * 4 + 1] = ok ? tbg[j * 4 + 1] : 0.f;
        g_cb[oidx * 4 + 2] = ok ? tbg[j * 4 + 2] : 0.f;
        g_cb[oidx * 4 + 3] = ok ? tbg[j * 4 + 3] : 0.f;
    }
}

// ---------------- multilevel ROI align (7x7, C=256), scalar ----------------
__global__ void roi_align_kernel(const float* __restrict__ f2, const float* __restrict__ f3,
                                 const float* __restrict__ f4, const float* __restrict__ f5,
                                 const float* __restrict__ f6) {
    int br = blockIdx.x;
    int b = br >> 9;
    int c = threadIdx.x;  // 256

    float y1 = g_rois[br * 4 + 0], x1 = g_rois[br * 4 + 1];
    float y2 = g_rois[br * 4 + 2], x2 = g_rois[br * 4 + 3];
    float h = y2 - y1, w = x2 - x1;
    float lvlf = floorf(log2f(sqrtf(fmaxf(h * w, 1e-8f)) / 224.0f + 1e-8f) + 4.0f);
    lvlf = fminf(fmaxf(lvlf, 2.0f), 6.0f);
    int li = (int)lvlf - 2;
    float stride = exp2f(lvlf);
    int S = 512 >> (li + 2);
    const float* f = (li == 0) ? f2 : (li == 1) ? f3 : (li == 2) ? f4 : (li == 3) ? f5 : f6;
    const float* fb = f + (size_t)b * S * S * 256;

    for (int iy = 0; iy < 7; iy++) {
        float ty = (iy + 0.5f) / 7.0f;
        float fy = (y1 + ty * h) / stride - 0.5f;
        float y0f = floorf(fy);
        float wy = fy - y0f;
        int yy0 = min(max((int)y0f, 0), S - 1);
        int yy1 = min(yy0 + 1, S - 1);
        for (int ix = 0; ix < 7; ix++) {
            float tx = (ix + 0.5f) / 7.0f;
            float fx = (x1 + tx * w) / stride - 0.5f;
            float x0f = floorf(fx);
            float wx = fx - x0f;
            int xx0 = min(max((int)x0f, 0), S - 1);
            int xx1 = min(xx0 + 1, S - 1);
            float v00 = fb[((size_t)yy0 * S + xx0) * 256 + c];
            float v01 = fb[((size_t)yy0 * S + xx1) * 256 + c];
            float v10 = fb[((size_t)yy1 * S + xx0) * 256 + c];
            float v11 = fb[((size_t)yy1 * S + xx1) * 256 + c];
            float v = v00 * (1 - wy) * (1 - wx) + v01 * (1 - wy) * wx +
                      v10 * wy * (1 - wx) + v11 * wy * wx;
            g_x[(size_t)br * 12544 + (iy * 7 + ix) * 256 + c] = v;
        }
    }
}

// ---------------- fp32 tiled SGEMM 64x64: C = [relu](A @ W + bias) ----------------
__global__ void gemm_kernel(int mode, const float* __restrict__ W, const float* __restrict__ bias,
                            int K, int N, int do_relu) {
    const float* A;
    float* C;
    if (mode == 0)      { A = g_x;  C = g_h1; }
    else if (mode == 1) { A = g_h1; C = g_h2; }
    else if (mode == 2) { A = g_h2; C = g_cls; }
    else                { A = g_h2; C = g_boxr; }

    __shared__ float4 As4[16 * 17];   // As[16][68]
    __shared__ float4 Bs4[16 * 16];   // Bs[16][64]
    float* As = (float*)As4;
    float* Bs = (float*)Bs4;
    int tid = threadIdx.x;  // 256
    int tx = tid & 15, ty = tid >> 4;
    int m0 = blockIdx.y * 64, n0 = blockIdx.x * 64;

    float acc[4][4] = {};
    for (int k0 = 0; k0 < K; k0 += 16) {
#pragma unroll
        for (int l = 0; l < 4; l++) {
            int e = tid + 256 * l;
            int r = e >> 4, cc = e & 15;
            As[cc * 68 + r] = A[(size_t)(m0 + r) * K + k0 + cc];
        }
#pragma unroll
        for (int l = 0; l < 4; l++) {
            int e = tid + 256 * l;
            int r = e >> 6, cc = e & 63;
            Bs[r * 64 + cc] = (n0 + cc < N) ? W[(size_t)(k0 + r) * N + n0 + cc] : 0.f;
        }
        __syncthreads();
#pragma unroll
        for (int k = 0; k < 16; k++) {
            float4 av = *(const float4*)&As[k * 68 + ty * 4];
            float4 bv = *(const float4*)&Bs[k * 64 + tx * 4];
            float a[4] = {av.x, av.y, av.z, av.w};
            float bq[4] = {bv.x, bv.y, bv.z, bv.w};
#pragma unroll
            for (int i = 0; i < 4; i++)
#pragma unroll
                for (int j = 0; j < 4; j++) acc[i][j] += a[i] * bq[j];
        }
        __syncthreads();
    }
#pragma unroll
    for (int i = 0; i < 4; i++) {
        int m = m0 + ty * 4 + i;
#pragma unroll
        for (int j = 0; j < 4; j++) {
            int n = n0 + tx * 4 + j;
            if (n < N) {
                float v = acc[i][j] + bias[n];
                if (do_relu) v = fmaxf(v, 0.f);
                C[(size_t)m * N + n] = v;
            }
        }
    }
}

// ---------------- softmax over 91 classes + per-class box decode + clip ----------------
__global__ void softmax_decode_kernel(const float* __restrict__ info) {
    int br = blockIdx.x;
    int b = br >> 9;
    int r = br & 511;
    int tid = threadIdx.x;  // 96

    __shared__ float sl[91];
    __shared__ float smax, ssum;
    const float* lg = g_cls + (size_t)br * 91;
    if (tid < 91) sl[tid] = lg[tid];
    __syncthreads();
    if (tid == 0) {
        float m = sl[0];
        for (int i = 1; i < 91; i++) m = fmaxf(m, sl[i]);
        float s = 0.f;
        for (int i = 0; i < 91; i++) s += expf(sl[i] - m);
        smax = m;
        ssum = s;
    }
    __syncthreads();

    float ry1 = g_rois[br * 4 + 0], rx1 = g_rois[br * 4 + 1];
    float ry2 = g_rois[br * 4 + 2], rx2 = g_rois[br * 4 + 3];
    float ah = ry2 - ry1, aw = rx2 - rx1;
    float acy = ry1 + 0.5f * ah, acx = rx1 + 0.5f * aw;
    float ih = info[b * 5 + 0], iw = info[b * 5 + 1];

    if (tid < 90) {
        int j = tid + 1;
        float p = expf(sl[j] - smax) / ssum;
        const float* dl = g_boxr + (size_t)br * 364 + j * 4;
        float dy = dl[0] / 10.f, dx = dl[1] / 10.f;
        float dh = fminf(dl[2] / 5.f, BBOX_CLIP), dw = fminf(dl[3] / 5.f, BBOX_CLIP);
        float cy = dy * ah + acy, cx = dx * aw + acx;
        float hh = expf(dh) * ah, ww = expf(dw) * aw;
        float by1 = cy - 0.5f * hh, bx1 = cx - 0.5f * ww;
        float by2 = cy + 0.5f * hh, bx2 = cx + 0.5f * ww;
        by1 = fminf(fmaxf(by1, 0.f), ih);
        bx1 = fminf(fmaxf(bx1, 0.f), iw);
        by2 = fminf(fmaxf(by2, 0.f), ih);
        bx2 = fminf(fmaxf(bx2, 0.f), iw);
        int oi = r * 90 + tid;
        g_sc[b * 46080 + oi] = p;
        size_t bo = ((size_t)b * 46080 + oi) * 4;
        g_bx[bo + 0] = by1;
        g_bx[bo + 1] = bx1;
        g_bx[bo + 2] = by2;
        g_bx[bo + 3] = bx2;
    }
}

// ---------------- detection NMS (grid 2, 256 threads) + output ----------------
__global__ void nms_det_kernel(float* __restrict__ out) {
    int b = blockIdx.x;
    int tid = threadIdx.x;  // 256
    __shared__ float ob[500 * 4];
    __shared__ float ss[500];
    __shared__ float scls[500];
    __shared__ int sidx[100];
    __shared__ unsigned char sval[100];
    __shared__ float rv[8];
    __shared__ int ri[8];
    __shared__ int cnt;

    for (int j = tid; j < 500; j += 256) {
        float cls = (float)(g_dti[b * 500 + j] % 90 + 1);
        scls[j] = cls;
        ss[j] = g_dts[b * 500 + j];
        float off = cls * 1024.f;
        ob[j * 4 + 0] = g_dtb[(b * 500 + j) * 4 + 0] + off;
        ob[j * 4 + 1] = g_dtb[(b * 500 + j) * 4 + 1] + off;
        ob[j * 4 + 2] = g_dtb[(b * 500 + j) * 4 + 2] + off;
        ob[j * 4 + 3] = g_dtb[(b * 500 + j) * 4 + 3] + off;
    }
    if (tid == 0) cnt = 0;
    __syncthreads();

    for (int it = 0; it < 100; it++) {
        float bv = NEG_INF;
        int bi = 0x7FFFFFFF;
        for (int j = tid; j < 500; j += 256) {
            float v = ss[j];
            if (v > bv) { bv = v; bi = j; }
        }
#pragma unroll
        for (int o = 16; o; o >>= 1) {
            float ov = __shfl_down_sync(0xFFFFFFFFu, bv, o);
            int oidx = __shfl_down_sync(0xFFFFFFFFu, bi, o);
            if (ov > bv || (ov == bv && oidx < bi)) { bv = ov; bi = oidx; }
        }
        if ((tid & 31) == 0) { rv[tid >> 5] = bv; ri[tid >> 5] = bi; }
        __syncthreads();
        if (tid < 32) {
            bv = (tid < 8) ? rv[tid] : NEG_INF;
            bi = (tid < 8) ? ri[tid] : 0x7FFFFFFF;
#pragma unroll
            for (int o = 4; o; o >>= 1) {
                float ov = __shfl_down_sync(0xFFFFFFFFu, bv, o);
                int oidx = __shfl_down_sync(0xFFFFFFFFu, bi, o);
                if (ov > bv || (ov == bv && oidx < bi)) { bv = ov; bi = oidx; }
            }
            if (tid == 0) { rv[0] = bv; ri[0] = bi; }
        }
        __syncthreads();
        int j = ri[0];
        float vj = rv[0];
        if (tid == 0) { sidx[it] = j; sval[it] = (vj > VALID_THR) ? 1 : 0; }
        float jy1 = ob[j * 4 + 0], jx1 = ob[j * 4 + 1];
        float jy2 = ob[j * 4 + 2], jx2 = ob[j * 4 + 3];
        __syncthreads();
        for (int t = tid; t < 500; t += 256) {
            float u = iou_f(jy1, jx1, jy2, jx2,
                            ob[t * 4 + 0], ob[t * 4 + 1], ob[t * 4 + 2], ob[t * 4 + 3]);
            if (u >= 0.5f) ss[t] = SUPPRESS;
        }
        __syncthreads();
    }

    for (int i = tid; i < 100; i += 256) {
        int j = sidx[i];
        bool ok = sval[i] != 0;
        for (int d = 0; d < 4; d++)
            out[2 + (b * 100 + i) * 4 + d] = ok ? g_dtb[(b * 500 + j) * 4 + d] : 0.f;
        out[802 + b * 100 + i] = ok ? scls[j] : 0.f;
        out[1002 + b * 100 + i] = ok ? g_dts[b * 500 + j] : 0.f;
        if (ok) atomicAdd(&cnt, 1);
    }
    __syncthreads();
    if (tid == 0) out[b] = (float)cnt;
}

// ---------------- host launch ----------------
extern "C" void kernel_launch(void* const* d_in, const int* in_sizes, int n_in,
                              void* d_out, int out_size) {
    const float* fpn[5] = {(const float*)d_in[0], (const float*)d_in[1], (const float*)d_in[2],
                           (const float*)d_in[3], (const float*)d_in[4]};
    const float* info = (const float*)d_in[5];
    const float* rpn_conv_w = (const float*)d_in[6];
    const float* rpn_conv_b = (const float*)d_in[7];
    const float* rpn_cls_w = (const float*)d_in[8];
    const float* rpn_cls_b = (const float*)d_in[9];
    const float* rpn_box_w = (const float*)d_in[10];
    const float* rpn_box_b = (const float*)d_in[11];
    const float* fc1_w = (const float*)d_in[12];
    const float* fc1_b = (const float*)d_in[13];
    const float* fc2_w = (const float*)d_in[14];
    const float* fc2_b = (const float*)d_in[15];
    const float* cls_w = (const float*)d_in[16];
    const float* cls_b = (const float*)d_in[17];
    const float* boxr_w = (const float*)d_in[18];
    const float* boxr_b = (const float*)d_in[19];
    float* out = (float*)d_out;

    conv3x3_relu_kernel<<<2728, 64>>>(fpn[0], fpn[1], fpn[2], fpn[3], fpn[4],
                                      rpn_conv_w, rpn_conv_b);
    rpn_head_kernel<<<2728, 256>>>(rpn_cls_w, rpn_cls_b, rpn_box_w, rpn_box_b);
    rpn_decode_kernel<<<(2 * 65472 + 255) / 256, 256>>>(info);

    topk_radix_kernel<<<10, 1024>>>(0);
    nms_rpn_kernel<<<10, 256>>>();
    topk_radix_kernel<<<2, 1024>>>(1);

    roi_align_kernel<<<1024, 256>>>(fpn[0], fpn[1], fpn[2], fpn[3], fpn[4]);

    gemm_kernel<<<dim3(16, 16), 256>>>(0, fc1_w, fc1_b, 12544, 1024, 1);
    gemm_kernel<<<dim3(16, 16), 256>>>(1, fc2_w, fc2_b, 1024, 1024, 1);
    gemm_kernel<<<dim3(2, 16), 256>>>(2, cls_w, cls_b, 1024, 91, 0);
    gemm_kernel<<<dim3(6, 16), 256>>>(3, boxr_w, boxr_b, 1024, 364, 0);

    softmax_decode_kernel<<<1024, 96>>>(info);

    topk_radix_kernel<<<2, 1024>>>(2);
    nms_det_kernel<<<2, 256>>>(out);
}

// round 16
// speedup vs baseline: 1.0579x; 1.0579x over previous
#include <cuda_runtime.h>
#include <math.h>
#include <stdint.h>

#define NEG_INF   (-3.402823466e38f)
#define SUPPRESS  (-1e10f)
#define VALID_THR (-1e9f)
#define BBOX_CLIP 4.135166556742356f

// level tables
__device__ __constant__ int c_S[5]      = {128, 64, 32, 16, 8};
__device__ __constant__ int c_cumB[6]   = {0, 2048, 2560, 2688, 2720, 2728};          // conv blocks (16 px/blk)
__device__ __constant__ int c_Poff[6]   = {0, 32768, 40960, 43008, 43520, 43648};     // pixel base (both b)
__device__ __constant__ int c_Aoff[6]   = {0, 49152, 61440, 64512, 65280, 65472};     // anchor base per b
__device__ __constant__ int c_nl[5]     = {49152, 12288, 3072, 768, 192};
__device__ __constant__ int c_kl[5]     = {400, 400, 400, 400, 192};

// ---------------- scratch ----------------
__device__ float g_hfeat[43648 * 256];           // all-level conv output (pixel-major)
__device__ float g_raw[43648 * 16];              // per-pixel 15 head outputs (padded 16)
__device__ float g_scores[2 * 65472];
__device__ float g_boxes[2 * 65472 * 4];
__device__ float g_ts[2 * 5 * 400];
__device__ float g_tb[2 * 5 * 400 * 4];
__device__ int   g_ti[2 * 5 * 400];
__device__ float g_cs[2 * 640];
__device__ float g_cb[2 * 640 * 4];
__device__ float g_rois[2 * 512 * 4];
__device__ float g_dummy_s[2 * 512];
__device__ int   g_dummy_i[2 * 512];
__device__ float g_x[2 * 512 * 12544];
__device__ float g_h1[2 * 512 * 1024];
__device__ float g_h2[2 * 512 * 1024];
__device__ float g_cls[2 * 512 * 91];
__device__ float g_boxr[2 * 512 * 364];
__device__ float g_sc[2 * 46080];
__device__ float g_bx[2 * 46080 * 4];
__device__ float g_dts[2 * 500];
__device__ float g_dtb[2 * 500 * 4];
__device__ int   g_dti[2 * 500];

__device__ __forceinline__ float iou_f(float ay1, float ax1, float ay2, float ax2,
                                       float by1, float bx1, float by2, float bx2) {
    float areaA = fmaxf(ay2 - ay1, 0.f) * fmaxf(ax2 - ax1, 0.f);
    float areaB = fmaxf(by2 - by1, 0.f) * fmaxf(bx2 - bx1, 0.f);
    float iy1 = fmaxf(ay1, by1), ix1 = fmaxf(ax1, bx1);
    float iy2 = fminf(ay2, by2), ix2 = fminf(ax2, bx2);
    float inter = fmaxf(iy2 - iy1, 0.f) * fmaxf(ix2 - ix1, 0.f);
    return inter / (areaA + areaB - inter + 1e-8f);
}

__device__ __forceinline__ unsigned int flip_f(float f) {
    unsigned int u = __float_as_uint(f);
    return u ^ ((u & 0x80000000u) ? 0xFFFFFFFFu : 0x80000000u);
}

// ---------------- batched RPN 3x3 conv + relu (16 px/block, 128 threads, 2 co/thread, == R13) ----------------
__global__ void conv3x3_relu_kernel(const float* __restrict__ f2, const float* __restrict__ f3,
                                    const float* __restrict__ f4, const float* __restrict__ f5,
                                    const float* __restrict__ f6,
                                    const float* __restrict__ w, const float* __restrict__ bias) {
    int bid = blockIdx.x;
    int lvl = 0;
#pragma unroll
    for (int l = 1; l < 5; l++) if (bid >= c_cumB[l]) lvl = l;
    int S = c_S[lvl];
    int local = bid - c_cumB[lvl];
    int xt_count = S >> 3;
    int yt_count = S >> 1;
    int b = local / (xt_count * yt_count);
    int rem = local % (xt_count * yt_count);
    int y0 = (rem / xt_count) * 2;
    int xt = (rem % xt_count) * 8;
    const float* in = (lvl == 0) ? f2 : (lvl == 1) ? f3 : (lvl == 2) ? f4 : (lvl == 3) ? f5 : f6;

    int co = threadIdx.x;                        // 0..127 ; owns co and co+128
    __shared__ float4 s4buf[4 * 10 * 64];        // 40 KB
    float* sIn = (float*)s4buf;
    for (int idx = threadIdx.x; idx < 4 * 10 * 64; idx += 128) {
        int c4 = idx & 63;
        int xx = (idx >> 6) % 10;
        int r = idx / (10 * 64);
        int yy = y0 - 1 + r;
        int gx = xt - 1 + xx;
        float4 v = make_float4(0.f, 0.f, 0.f, 0.f);
        if (yy >= 0 && yy < S && gx >= 0 && gx < S)
            v = ((const float4*)(in + (((size_t)b * S + yy) * S + gx) * 256))[c4];
        s4buf[idx] = v;
    }
    __syncthreads();

    float acc0[16], acc1[16];
    float bv0 = bias[co];
    float bv1 = bias[co + 128];
#pragma unroll
    for (int p = 0; p < 16; p++) { acc0[p] = bv0; acc1[p] = bv1; }

    for (int kh = 0; kh < 3; kh++) {
        for (int kw = 0; kw < 3; kw++) {
            const float* wp = w + ((kh * 3 + kw) * 256) * 256 + co;
            for (int ci = 0; ci < 256; ci += 4) {
                float w00 = __ldg(wp + (ci + 0) * 256);
                float w01 = __ldg(wp + (ci + 1) * 256);
                float w02 = __ldg(wp + (ci + 2) * 256);
                float w03 = __ldg(wp + (ci + 3) * 256);
                float w10 = __ldg(wp + (ci + 0) * 256 + 128);
                float w11 = __ldg(wp + (ci + 1) * 256 + 128);
                float w12 = __ldg(wp + (ci + 2) * 256 + 128);
                float w13 = __ldg(wp + (ci + 3) * 256 + 128);
#pragma unroll
                for (int p = 0; p < 16; p++) {
                    int py = p >> 3, px = p & 7;
                    float4 sv = *(const float4*)&sIn[((py + kh) * 10 + (px + kw)) * 256 + ci];
                    acc0[p] = fmaf(sv.x, w00, acc0[p]);
                    acc0[p] = fmaf(sv.y, w01, acc0[p]);
                    acc0[p] = fmaf(sv.z, w02, acc0[p]);
                    acc0[p] = fmaf(sv.w, w03, acc0[p]);
                    acc1[p] = fmaf(sv.x, w10, acc1[p]);
                    acc1[p] = fmaf(sv.y, w11, acc1[p]);
                    acc1[p] = fmaf(sv.z, w12, acc1[p]);
                    acc1[p] = fmaf(sv.w, w13, acc1[p]);
                }
            }
        }
    }
#pragma unroll
    for (int p = 0; p < 16; p++) {
        int py = p >> 3, px = p & 7;
        size_t pixel = (size_t)c_Poff[lvl] + ((size_t)b * S + (y0 + py)) * S + (xt + px);
        g_hfeat[pixel * 256 + co] = fmaxf(acc0[p], 0.f);
        g_hfeat[pixel * 256 + co + 128] = fmaxf(acc1[p], 0.f);
    }
}

// ---------------- RPN 1x1 heads: 16 pixels/block, features staged once in smem ----------------
__global__ void rpn_head_kernel(const float* __restrict__ cw, const float* __restrict__ cb,
                                const float* __restrict__ bw, const float* __restrict__ bb) {
    __shared__ float sf[16 * 260];
    int p0 = blockIdx.x * 16;
    int tid = threadIdx.x;                       // 256

    for (int i = tid; i < 16 * 64; i += 256) {
        int row = i >> 6, c4 = i & 63;
        float4 v = ((const float4*)(g_hfeat + (size_t)(p0 + row) * 256))[c4];
        *(float4*)&sf[row * 260 + c4 * 4] = v;
    }
    __syncthreads();

    int p_local = tid >> 4;
    int o = tid & 15;
    if (o < 15) {
        float a;
        const float* wv;
        int st;
        if (o < 3) { a = cb[o]; wv = cw + o; st = 3; }
        else       { a = bb[o - 3]; wv = bw + (o - 3); st = 12; }
        const float* fp = sf + p_local * 260;
        for (int ci = 0; ci < 256; ci++) a += fp[ci] * __ldg(wv + ci * st);
        g_raw[(size_t)(p0 + p_local) * 16 + o] = a;
    }
}

// ---------------- RPN decode over all anchors ----------------
__global__ void rpn_decode_kernel(const float* __restrict__ info) {
    int t = blockIdx.x * blockDim.x + threadIdx.x;
    if (t >= 2 * 65472) return;
    int b = t / 65472;
    int r = t % 65472;
    int lvl = 0;
#pragma unroll
    for (int l = 1; l < 5; l++) if (r >= c_Aoff[l]) lvl = l;
    int local = r - c_Aoff[lvl];
    int hw = local / 3;
    int a = local % 3;
    int S = c_S[lvl];
    size_t p = (size_t)c_Poff[lvl] + (size_t)b * S * S + hw;

    const float* rp = g_raw + p * 16;
    float logit = rp[a];
    float d0 = rp[3 + a * 4 + 0], d1 = rp[3 + a * 4 + 1];
    float d2 = rp[3 + a * 4 + 2], d3 = rp[3 + a * 4 + 3];

    float score = 1.f / (1.f + expf(-logit));

    int stride = 4 << lvl;
    int iy = hw / S, ix = hw % S;
    const double AY[3] = {1.0, 1.4, 0.7};
    const double AX[3] = {1.0, 0.7, 1.4};
    double cyd = (iy + 0.5) * (double)stride;
    double cxd = (ix + 0.5) * (double)stride;
    double hd = 8.0 * (double)stride * AY[a];
    double wd = 8.0 * (double)stride * AX[a];
    float ay1 = (float)(cyd - hd / 2), ax1 = (float)(cxd - wd / 2);
    float ay2 = (float)(cyd + hd / 2), ax2 = (float)(cxd + wd / 2);

    float ah = ay2 - ay1, aw = ax2 - ax1;
    float acy = ay1 + 0.5f * ah, acx = ax1 + 0.5f * aw;

    float dh = fminf(d2, BBOX_CLIP), dw = fminf(d3, BBOX_CLIP);
    float ncy = d0 * ah + acy;
    float ncx = d1 * aw + acx;
    float nh = expf(dh) * ah;
    float nw = expf(dw) * aw;
    float y1 = ncy - 0.5f * nh, x1 = ncx - 0.5f * nw;
    float y2 = ncy + 0.5f * nh, x2 = ncx + 0.5f * nw;

    float ih = info[b * 5 + 0], iw = info[b * 5 + 1];
    y1 = fminf(fmaxf(y1, 0.f), ih);
    x1 = fminf(fmaxf(x1, 0.f), iw);
    y2 = fminf(fmaxf(y2, 0.f), ih);
    x2 = fminf(fmaxf(x2, 0.f), iw);

    int idx = b * 65472 + r;
    g_scores[idx] = score;
    g_boxes[idx * 4 + 0] = y1;
    g_boxes[idx * 4 + 1] = x1;
    g_boxes[idx * 4 + 2] = y2;
    g_boxes[idx * 4 + 3] = x2;
}

// ---------------- exact top-k via 64-bit radix select + bitonic sort ----------------
__global__ void topk_radix_kernel(int mode) {
    int tid = threadIdx.x;  // 1024
    const float* sc;
    const float* bxp;
    float* os;
    float* ob;
    int* oi;
    int n, k;
    if (mode == 0) {
        int b = blockIdx.x / 5, lvl = blockIdx.x % 5;
        sc = g_scores + b * 65472 + c_Aoff[lvl];
        bxp = g_boxes + (size_t)(b * 65472 + c_Aoff[lvl]) * 4;
        os = g_ts + (b * 5 + lvl) * 400;
        ob = g_tb + (size_t)(b * 5 + lvl) * 1600;
        oi = g_ti + (b * 5 + lvl) * 400;
        n = c_nl[lvl];
        k = c_kl[lvl];
    } else if (mode == 1) {
        int b = blockIdx.x;
        sc = g_cs + b * 640;
        bxp = g_cb + (size_t)b * 2560;
        os = g_dummy_s + b * 512;
        ob = g_rois + (size_t)b * 2048;
        oi = g_dummy_i + b * 512;
        n = 640; k = 512;
    } else {
        int b = blockIdx.x;
        sc = g_sc + b * 46080;
        bxp = g_bx + (size_t)b * 46080 * 4;
        os = g_dts + b * 500;
        ob = g_dtb + (size_t)b * 2000;
        oi = g_dti + b * 500;
        n = 46080; k = 500;
    }

    __shared__ unsigned int hist[256];
    __shared__ unsigned int suffix[256];
    __shared__ int s_krem, s_krem_next, s_chosen;
    __shared__ unsigned long long skeys[512];
    __shared__ int s_cnt;

    if (tid == 0) { s_krem = k; s_cnt = 0; }
    __syncthreads();

    unsigned long long pref = 0;
    for (int p = 7; p >= 0; p--) {
        if (tid < 256) hist[tid] = 0;
        __syncthreads();
        for (int j = tid; j < n; j += 1024) {
            unsigned long long key = (((unsigned long long)flip_f(sc[j])) << 32) | (unsigned int)(~(unsigned int)j);
            bool okc = (p == 7) || ((key >> (((unsigned)p + 1u) * 8u)) == pref);
            if (okc) atomicAdd(&hist[(unsigned)(key >> ((unsigned)p * 8u)) & 255u], 1u);
        }
        __syncthreads();
        if (tid < 256) suffix[tid] = hist[tid];
        __syncthreads();
        for (int d = 1; d < 256; d <<= 1) {
            unsigned v = 0;
            if (tid < 256) v = suffix[tid] + ((tid + d < 256) ? suffix[tid + d] : 0u);
            __syncthreads();
            if (tid < 256) suffix[tid] = v;
            __syncthreads();
        }
        if (tid < 256) {
            unsigned above = (tid == 255) ? 0u : suffix[tid + 1];
            if (suffix[tid] >= (unsigned)s_krem && above < (unsigned)s_krem) {
                s_chosen = tid;
                s_krem_next = s_krem - (int)above;
            }
        }
        __syncthreads();
        pref = (pref << 8) | (unsigned)s_chosen;
        if (tid == 0) s_krem = s_krem_next;
        __syncthreads();
    }
    unsigned long long kth = pref;

    for (int j = tid; j < n; j += 1024) {
        unsigned long long key = (((unsigned long long)flip_f(sc[j])) << 32) | (unsigned int)(~(unsigned int)j);
        if (key >= kth) skeys[atomicAdd(&s_cnt, 1)] = key;
    }
    __syncthreads();
    for (int idx = tid; idx < 512; idx += 1024)
        if (idx >= k) skeys[idx] = 0ull;
    __syncthreads();

    for (int size = 2; size <= 512; size <<= 1) {
        for (int stride = size >> 1; stride; stride >>= 1) {
            for (int idx = tid; idx < 512; idx += 1024) {
                int partner = idx ^ stride;
                if (partner > idx) {
                    bool dirDesc = ((idx & size) == 0);
                    unsigned long long a = skeys[idx], c2 = skeys[partner];
                    bool sw = dirDesc ? (a < c2) : (a > c2);
                    if (sw) { skeys[idx] = c2; skeys[partner] = a; }
                }
            }
            __syncthreads();
        }
    }

    for (int it = tid; it < k; it += 1024) {
        unsigned long long key = skeys[it];
        int j = (int)(~(unsigned int)(key & 0xFFFFFFFFull));
        os[it] = sc[j];
        oi[it] = j;
        ob[it * 4 + 0] = bxp[j * 4 + 0];
        ob[it * 4 + 1] = bxp[j * 4 + 1];
        ob[it * 4 + 2] = bxp[j * 4 + 2];
        ob[it * 4 + 3] = bxp[j * 4 + 3];
    }
}

// ---------------- batched RPN NMS (grid 10, 256 threads) ----------------
__global__ void nms_rpn_kernel() {
    int task = blockIdx.x;
    int b = task / 5, lvl = task % 5;
    int n = c_kl[lvl];
    int tid = threadIdx.x;  // 256
    __shared__ float sb[400 * 4];
    __shared__ float ss[400];
    __shared__ int sidx[128];
    __shared__ unsigned char sval[128];
    __shared__ float rv[8];
    __shared__ int ri[8];

    const float* tsg = g_ts + (b * 5 + lvl) * 400;
    const float* tbg = g_tb + (size_t)(b * 5 + lvl) * 1600;

    for (int j = tid; j < n; j += 256) {
        ss[j] = tsg[j];
        sb[j * 4 + 0] = tbg[j * 4 + 0];
        sb[j * 4 + 1] = tbg[j * 4 + 1];
        sb[j * 4 + 2] = tbg[j * 4 + 2];
        sb[j * 4 + 3] = tbg[j * 4 + 3];
    }
    __syncthreads();

    for (int it = 0; it < 128; it++) {
        float bv = NEG_INF;
        int bi = 0x7FFFFFFF;
        for (int j = tid; j < n; j += 256) {
            float v = ss[j];
            if (v > bv) { bv = v; bi = j; }
        }
#pragma unroll
        for (int o = 16; o; o >>= 1) {
            float ov = __shfl_down_sync(0xFFFFFFFFu, bv, o);
            int oidx = __shfl_down_sync(0xFFFFFFFFu, bi, o);
            if (ov > bv || (ov == bv && oidx < bi)) { bv = ov; bi = oidx; }
        }
        if ((tid & 31) == 0) { rv[tid >> 5] = bv; ri[tid >> 5] = bi; }
        __syncthreads();
        if (tid < 32) {
            bv = (tid < 8) ? rv[tid] : NEG_INF;
            bi = (tid < 8) ? ri[tid] : 0x7FFFFFFF;
#pragma unroll
            for (int o = 4; o; o >>= 1) {
                float ov = __shfl_down_sync(0xFFFFFFFFu, bv, o);
                int oidx = __shfl_down_sync(0xFFFFFFFFu, bi, o);
                if (ov > bv || (ov == bv && oidx < bi)) { bv = ov; bi = oidx; }
            }
            if (tid == 0) { rv[0] = bv; ri[0] = bi; }
        }
        __syncthreads();
        int j = ri[0];
        float vj = rv[0];
        if (tid == 0) { sidx[it] = j; sval[it] = (vj > VALID_THR) ? 1 : 0; }
        float jy1 = sb[j * 4 + 0], jx1 = sb[j * 4 + 1];
        float jy2 = sb[j * 4 + 2], jx2 = sb[j * 4 + 3];
        __syncthreads();
        for (int t = tid; t < n; t += 256) {
            float u = iou_f(jy1, jx1, jy2, jx2,
                            sb[t * 4 + 0], sb[t * 4 + 1], sb[t * 4 + 2], sb[t * 4 + 3]);
            if (u >= 0.7f) ss[t] = SUPPRESS;
        }
        __syncthreads();
    }

    for (int i = tid; i < 128; i += 256) {
        int j = sidx[i];
        bool ok = sval[i] != 0;
        int oidx = b * 640 + lvl * 128 + i;
        g_cs[oidx] = ok ? tsg[j] : SUPPRESS;
        g_cb[oidx * 4 + 0] = ok ? tbg[j * 4 + 0] : 0.f;
        g_cb[oidx * 4 + 1] = ok ? tbg[j * 4 + 1] : 0.f;
        g_cb[oidx * 4 + 2] = ok ? tbg[j * 4 + 2] : 0.f;
        g_cb[oidx * 4 + 3] = ok ? tbg[j * 4 + 3] : 0.f;
    }
}

// ---------------- multilevel ROI align (7x7, C=256), scalar ----------------
__global__ void roi_align_kernel(const float* __restrict__ f2, const float* __restrict__ f3,
                                 const float* __restrict__ f4, const float* __restrict__ f5,
                                 const float* __restrict__ f6) {
    int br = blockIdx.x;
    int b = br >> 9;
    int c = threadIdx.x;  // 256

    float y1 = g_rois[br * 4 + 0], x1 = g_rois[br * 4 + 1];
    float y2 = g_rois[br * 4 + 2], x2 = g_rois[br * 4 + 3];
    float h = y2 - y1, w = x2 - x1;
    float lvlf = floorf(log2f(sqrtf(fmaxf(h * w, 1e-8f)) / 224.0f + 1e-8f) + 4.0f);
    lvlf = fminf(fmaxf(lvlf, 2.0f), 6.0f);
    int li = (int)lvlf - 2;
    float stride = exp2f(lvlf);
    int S = 512 >> (li + 2);
    const float* f = (li == 0) ? f2 : (li == 1) ? f3 : (li == 2) ? f4 : (li == 3) ? f5 : f6;
    const float* fb = f + (size_t)b * S * S * 256;

    for (int iy = 0; iy < 7; iy++) {
        float ty = (iy + 0.5f) / 7.0f;
        float fy = (y1 + ty * h) / stride - 0.5f;
        float y0f = floorf(fy);
        float wy = fy - y0f;
        int yy0 = min(max((int)y0f, 0), S - 1);
        int yy1 = min(yy0 + 1, S - 1);
        for (int ix = 0; ix < 7; ix++) {
            float tx = (ix + 0.5f) / 7.0f;
            float fx = (x1 + tx * w) / stride - 0.5f;
            float x0f = floorf(fx);
            float wx = fx - x0f;
            int xx0 = min(max((int)x0f, 0), S - 1);
            int xx1 = min(xx0 + 1, S - 1);
            float v00 = fb[((size_t)yy0 * S + xx0) * 256 + c];
            float v01 = fb[((size_t)yy0 * S + xx1) * 256 + c];
            float v10 = fb[((size_t)yy1 * S + xx0) * 256 + c];
            float v11 = fb[((size_t)yy1 * S + xx1) * 256 + c];
            float v = v00 * (1 - wy) * (1 - wx) + v01 * (1 - wy) * wx +
                      v10 * wy * (1 - wx) + v11 * wy * wx;
            g_x[(size_t)br * 12544 + (iy * 7 + ix) * 256 + c] = v;
        }
    }
}

// ---------------- fp32 tiled SGEMM 64x64, N=1024, float4 staging (fc1 / fc2) ----------------
// FMA loop and smem layout identical to gemm_kernel -> bitwise same results.
__global__ void gemm_big_kernel(int mode, const float* __restrict__ W,
                                const float* __restrict__ bias, int K) {
    const float* A = (mode == 0) ? g_x : g_h1;
    float* C = (mode == 0) ? g_h1 : g_h2;
    const int N = 1024;

    __shared__ float4 As4[16 * 17];   // As[16][68]
    __shared__ float4 Bs4[16 * 16];   // Bs[16][64]
    float* As = (float*)As4;
    float* Bs = (float*)Bs4;
    int tid = threadIdx.x;  // 256
    int tx = tid & 15, ty = tid >> 4;
    int m0 = blockIdx.y * 64, n0 = blockIdx.x * 64;

    float acc[4][4] = {};
    for (int k0 = 0; k0 < K; k0 += 16) {
        {   // A: 64 rows x 16 k = 256 float4 loads (1 per thread)
            int row = tid & 63;
            int quad = tid >> 6;          // 0..3
            float4 v = *(const float4*)(A + (size_t)(m0 + row) * K + k0 + quad * 4);
            As[(quad * 4 + 0) * 68 + row] = v.x;
            As[(quad * 4 + 1) * 68 + row] = v.y;
            As[(quad * 4 + 2) * 68 + row] = v.z;
            As[(quad * 4 + 3) * 68 + row] = v.w;
        }
        {   // B: 16 k x 64 n = 256 float4 loads (1 per thread)
            int r = tid >> 4, c4 = tid & 15;
            float4 v = *(const float4*)(W + (size_t)(k0 + r) * N + n0 + c4 * 4);
            *(float4*)&Bs[r * 64 + c4 * 4] = v;
        }
        __syncthreads();
#pragma unroll
        for (int k = 0; k < 16; k++) {
            float4 av = *(const float4*)&As[k * 68 + ty * 4];
            float4 bv = *(const float4*)&Bs[k * 64 + tx * 4];
            float a[4] = {av.x, av.y, av.z, av.w};
            float bq[4] = {bv.x, bv.y, bv.z, bv.w};
#pragma unroll
            for (int i = 0; i < 4; i++)
#pragma unroll
                for (int j = 0; j < 4; j++) acc[i][j] += a[i] * bq[j];
        }
        __syncthreads();
    }
#pragma unroll
    for (int i = 0; i < 4; i++) {
        int m = m0 + ty * 4 + i;
#pragma unroll
        for (int j = 0; j < 4; j++) {
            int n = n0 + tx * 4 + j;
            C[(size_t)m * N + n] = fmaxf(acc[i][j] + bias[n], 0.f);
        }
    }
}

// ---------------- fp32 tiled SGEMM 64x64, bounds-checked (cls / boxr) ----------------
__global__ void gemm_kernel(int mode, const float* __restrict__ W, const float* __restrict__ bias,
                            int K, int N, int do_relu) {
    const float* A = g_h2;
    float* C = (mode == 2) ? g_cls : g_boxr;

    __shared__ float4 As4[16 * 17];   // As[16][68]
    __shared__ float4 Bs4[16 * 16];   // Bs[16][64]
    float* As = (float*)As4;
    float* Bs = (float*)Bs4;
    int tid = threadIdx.x;  // 256
    int tx = tid & 15, ty = tid >> 4;
    int m0 = blockIdx.y * 64, n0 = blockIdx.x * 64;

    float acc[4][4] = {};
    for (int k0 = 0; k0 < K; k0 += 16) {
#pragma unroll
        for (int l = 0; l < 4; l++) {
            int e = tid + 256 * l;
            int r = e >> 4, cc = e & 15;
            As[cc * 68 + r] = A[(size_t)(m0 + r) * K + k0 + cc];
        }
#pragma unroll
        for (int l = 0; l < 4; l++) {
            int e = tid + 256 * l;
            int r = e >> 6, cc = e & 63;
            Bs[r * 64 + cc] = (n0 + cc < N) ? W[(size_t)(k0 + r) * N + n0 + cc] : 0.f;
        }
        __syncthreads();
#pragma unroll
        for (int k = 0; k < 16; k++) {
            float4 av = *(const float4*)&As[k * 68 + ty * 4];
            float4 bv = *(const float4*)&Bs[k * 64 + tx * 4];
            float a[4] = {av.x, av.y, av.z, av.w};
            float bq[4] = {bv.x, bv.y, bv.z, bv.w};
#pragma unroll
            for (int i = 0; i < 4; i++)
#pragma unroll
                for (int j = 0; j < 4; j++) acc[i][j] += a[i] * bq[j];
        }
        __syncthreads();
    }
#pragma unroll
    for (int i = 0; i < 4; i++) {
        int m = m0 + ty * 4 + i;
#pragma unroll
        for (int j = 0; j < 4; j++) {
            int n = n0 + tx * 4 + j;
            if (n < N) {
                float v = acc[i][j] + bias[n];
                if (do_relu) v = fmaxf(v, 0.f);
                C[(size_t)m * N + n] = v;
            }
        }
    }
}

// ---------------- softmax over 91 classes + per-class box decode + clip ----------------
__global__ void softmax_decode_kernel(const float* __restrict__ info) {
    int br = blockIdx.x;
    int b = br >> 9;
    int r = br & 511;
    int tid = threadIdx.x;  // 96

    __shared__ float sl[91];
    __shared__ float smax, ssum;
    const float* lg = g_cls + (size_t)br * 91;
    if (tid < 91) sl[tid] = lg[tid];
    __syncthreads();
    if (tid == 0) {
        float m = sl[0];
        for (int i = 1; i < 91; i++) m = fmaxf(m, sl[i]);
        float s = 0.f;
        for (int i = 0; i < 91; i++) s += expf(sl[i] - m);
        smax = m;
        ssum = s;
    }
    __syncthreads();

    float ry1 = g_rois[br * 4 + 0], rx1 = g_rois[br * 4 + 1];
    float ry2 = g_rois[br * 4 + 2], rx2 = g_rois[br * 4 + 3];
    float ah = ry2 - ry1, aw = rx2 - rx1;
    float acy = ry1 + 0.5f * ah, acx = rx1 + 0.5f * aw;
    float ih = info[b * 5 + 0], iw = info[b * 5 + 1];

    if (tid < 90) {
        int j = tid + 1;
        float p = expf(sl[j] - smax) / ssum;
        const float* dl = g_boxr + (size_t)br * 364 + j * 4;
        float dy = dl[0] / 10.f, dx = dl[1] / 10.f;
        float dh = fminf(dl[2] / 5.f, BBOX_CLIP), dw = fminf(dl[3] / 5.f, BBOX_CLIP);
        float cy = dy * ah + acy, cx = dx * aw + acx;
        float hh = expf(dh) * ah, ww = expf(dw) * aw;
        float by1 = cy - 0.5f * hh, bx1 = cx - 0.5f * ww;
        float by2 = cy + 0.5f * hh, bx2 = cx + 0.5f * ww;
        by1 = fminf(fmaxf(by1, 0.f), ih);
        bx1 = fminf(fmaxf(bx1, 0.f), iw);
        by2 = fminf(fmaxf(by2, 0.f), ih);
        bx2 = fminf(fmaxf(bx2, 0.f), iw);
        int oi = r * 90 + tid;
        g_sc[b * 46080 + oi] = p;
        size_t bo = ((size_t)b * 46080 + oi) * 4;
        g_bx[bo + 0] = by1;
        g_bx[bo + 1] = bx1;
        g_bx[bo + 2] = by2;
        g_bx[bo + 3] = bx2;
    }
}

// ---------------- detection NMS (grid 2, 256 threads) + output ----------------
__global__ void nms_det_kernel(float* __restrict__ out) {
    int b = blockIdx.x;
    int tid = threadIdx.x;  // 256
    __shared__ float ob[500 * 4];
    __shared__ float ss[500];
    __shared__ float scls[500];
    __shared__ int sidx[100];
    __shared__ unsigned char sval[100];
    __shared__ float rv[8];
    __shared__ int ri[8];
    __shared__ int cnt;

    for (int j = tid; j < 500; j += 256) {
        float cls = (float)(g_dti[b * 500 + j] % 90 + 1);
        scls[j] = cls;
        ss[j] = g_dts[b * 500 + j];
        float off = cls * 1024.f;
        ob[j * 4 + 0] = g_dtb[(b * 500 + j) * 4 + 0] + off;
        ob[j * 4 + 1] = g_dtb[(b * 500 + j) * 4 + 1] + off;
        ob[j * 4 + 2] = g_dtb[(b * 500 + j) * 4 + 2] + off;
        ob[j * 4 + 3] = g_dtb[(b * 500 + j) * 4 + 3] + off;
    }
    if (tid == 0) cnt = 0;
    __syncthreads();

    for (int it = 0; it < 100; it++) {
        float bv = NEG_INF;
        int bi = 0x7FFFFFFF;
        for (int j = tid; j < 500; j += 256) {
            float v = ss[j];
            if (v > bv) { bv = v; bi = j; }
        }
#pragma unroll
        for (int o = 16; o; o >>= 1) {
            float ov = __shfl_down_sync(0xFFFFFFFFu, bv, o);
            int oidx = __shfl_down_sync(0xFFFFFFFFu, bi, o);
            if (ov > bv || (ov == bv && oidx < bi)) { bv = ov; bi = oidx; }
        }
        if ((tid & 31) == 0) { rv[tid >> 5] = bv; ri[tid >> 5] = bi; }
        __syncthreads();
        if (tid < 32) {
            bv = (tid < 8) ? rv[tid] : NEG_INF;
            bi = (tid < 8) ? ri[tid] : 0x7FFFFFFF;
#pragma unroll
            for (int o = 4; o; o >>= 1) {
                float ov = __shfl_down_sync(0xFFFFFFFFu, bv, o);
                int oidx = __shfl_down_sync(0xFFFFFFFFu, bi, o);
                if (ov > bv || (ov == bv && oidx < bi)) { bv = ov; bi = oidx; }
            }
            if (tid == 0) { rv[0] = bv; ri[0] = bi; }
        }
        __syncthreads();
        int j = ri[0];
        float vj = rv[0];
        if (tid == 0) { sidx[it] = j; sval[it] = (vj > VALID_THR) ? 1 : 0; }
        float jy1 = ob[j * 4 + 0], jx1 = ob[j * 4 + 1];
        float jy2 = ob[j * 4 + 2], jx2 = ob[j * 4 + 3];
        __syncthreads();
        for (int t = tid; t < 500; t += 256) {
            float u = iou_f(jy1, jx1, jy2, jx2,
                            ob[t * 4 + 0], ob[t * 4 + 1], ob[t * 4 + 2], ob[t * 4 + 3]);
            if (u >= 0.5f) ss[t] = SUPPRESS;
        }
        __syncthreads();
    }

    for (int i = tid; i < 100; i += 256) {
        int j = sidx[i];
        bool ok = sval[i] != 0;
        for (int d = 0; d < 4; d++)
            out[2 + (b * 100 + i) * 4 + d] = ok ? g_dtb[(b * 500 + j) * 4 + d] : 0.f;
        out[802 + b * 100 + i] = ok ? scls[j] : 0.f;
        out[1002 + b * 100 + i] = ok ? g_dts[b * 500 + j] : 0.f;
        if (ok) atomicAdd(&cnt, 1);
    }
    __syncthreads();
    if (tid == 0) out[b] = (float)cnt;
}

// ---------------- host launch ----------------
extern "C" void kernel_launch(void* const* d_in, const int* in_sizes, int n_in,
                              void* d_out, int out_size) {
    const float* fpn[5] = {(const float*)d_in[0], (const float*)d_in[1], (const float*)d_in[2],
                           (const float*)d_in[3], (const float*)d_in[4]};
    const float* info = (const float*)d_in[5];
    const float* rpn_conv_w = (const float*)d_in[6];
    const float* rpn_conv_b = (const float*)d_in[7];
    const float* rpn_cls_w = (const float*)d_in[8];
    const float* rpn_cls_b = (const float*)d_in[9];
    const float* rpn_box_w = (const float*)d_in[10];
    const float* rpn_box_b = (const float*)d_in[11];
    const float* fc1_w = (const float*)d_in[12];
    const float* fc1_b = (const float*)d_in[13];
    const float* fc2_w = (const float*)d_in[14];
    const float* fc2_b = (const float*)d_in[15];
    const float* cls_w = (const float*)d_in[16];
    const float* cls_b = (const float*)d_in[17];
    const float* boxr_w = (const float*)d_in[18];
    const float* boxr_b = (const float*)d_in[19];
    float* out = (float*)d_out;

    conv3x3_relu_kernel<<<2728, 128>>>(fpn[0], fpn[1], fpn[2], fpn[3], fpn[4],
                                       rpn_conv_w, rpn_conv_b);
    rpn_head_kernel<<<2728, 256>>>(rpn_cls_w, rpn_cls_b, rpn_box_w, rpn_box_b);
    rpn_decode_kernel<<<(2 * 65472 + 255) / 256, 256>>>(info);

    topk_radix_kernel<<<10, 1024>>>(0);
    nms_rpn_kernel<<<10, 256>>>();
    topk_radix_kernel<<<2, 1024>>>(1);

    roi_align_kernel<<<1024, 256>>>(fpn[0], fpn[1], fpn[2], fpn[3], fpn[4]);

    gemm_big_kernel<<<dim3(16, 16), 256>>>(0, fc1_w, fc1_b, 12544);
    gemm_big_kernel<<<dim3(16, 16), 256>>>(1, fc2_w, fc2_b, 1024);
    gemm_kernel<<<dim3(2, 16), 256>>>(2, cls_w, cls_b, 1024, 91, 0);
    gemm_kernel<<<dim3(6, 16), 256>>>(3, boxr_w, boxr_b, 1024, 364, 0);

    softmax_decode_kernel<<<1024, 96>>>(info);

    topk_radix_kernel<<<2, 1024>>>(2);
    nms_det_kernel<<<2, 256>>>(out);
}

// round 17
// speedup vs baseline: 1.1203x; 1.0590x over previous
#include <cuda_runtime.h>
#include <math.h>
#include <stdint.h>

#define NEG_INF   (-3.402823466e38f)
#define SUPPRESS  (-1e10f)
#define VALID_THR (-1e9f)
#define BBOX_CLIP 4.135166556742356f

// level tables
__device__ __constant__ int c_S[5]      = {128, 64, 32, 16, 8};
__device__ __constant__ int c_cumB[6]   = {0, 2048, 2560, 2688, 2720, 2728};          // conv blocks (16 px/blk)
__device__ __constant__ int c_Poff[6]   = {0, 32768, 40960, 43008, 43520, 43648};     // pixel base (both b)
__device__ __constant__ int c_Aoff[6]   = {0, 49152, 61440, 64512, 65280, 65472};     // anchor base per b
__device__ __constant__ int c_nl[5]     = {49152, 12288, 3072, 768, 192};
__device__ __constant__ int c_kl[5]     = {400, 400, 400, 400, 192};

// ---------------- scratch ----------------
__device__ float g_hfeat[43648 * 256];           // all-level conv output (pixel-major)
__device__ float g_raw[43648 * 16];              // per-pixel 15 head outputs (padded 16)
__device__ float g_scores[2 * 65472];
__device__ float g_boxes[2 * 65472 * 4];
__device__ float g_ts[2 * 5 * 400];
__device__ float g_tb[2 * 5 * 400 * 4];
__device__ int   g_ti[2 * 5 * 400];
__device__ float g_cs[2 * 640];
__device__ float g_cb[2 * 640 * 4];
__device__ float g_rois[2 * 512 * 4];
__device__ float g_dummy_s[2 * 512];
__device__ int   g_dummy_i[2 * 512];
__device__ float g_x[2 * 512 * 12544];
__device__ float g_h1[2 * 512 * 1024];
__device__ float g_h2[2 * 512 * 1024];
__device__ float g_cls[2 * 512 * 91];
__device__ float g_boxr[2 * 512 * 364];
__device__ float g_sc[2 * 46080];
__device__ float g_bx[2 * 46080 * 4];
__device__ float g_dts[2 * 500];
__device__ float g_dtb[2 * 500 * 4];
__device__ int   g_dti[2 * 500];

__device__ __forceinline__ float iou_f(float ay1, float ax1, float ay2, float ax2,
                                       float by1, float bx1, float by2, float bx2) {
    float areaA = fmaxf(ay2 - ay1, 0.f) * fmaxf(ax2 - ax1, 0.f);
    float areaB = fmaxf(by2 - by1, 0.f) * fmaxf(bx2 - bx1, 0.f);
    float iy1 = fmaxf(ay1, by1), ix1 = fmaxf(ax1, bx1);
    float iy2 = fminf(ay2, by2), ix2 = fminf(ax2, bx2);
    float inter = fmaxf(iy2 - iy1, 0.f) * fmaxf(ix2 - ix1, 0.f);
    return inter / (areaA + areaB - inter + 1e-8f);
}

__device__ __forceinline__ unsigned int flip_f(float f) {
    unsigned int u = __float_as_uint(f);
    return u ^ ((u & 0x80000000u) ? 0xFFFFFFFFu : 0x80000000u);
}

// ---------------- batched RPN 3x3 conv + relu (16 px/block, 128 threads, 2 co/thread, == R13) ----------------
__global__ void conv3x3_relu_kernel(const float* __restrict__ f2, const float* __restrict__ f3,
                                    const float* __restrict__ f4, const float* __restrict__ f5,
                                    const float* __restrict__ f6,
                                    const float* __restrict__ w, const float* __restrict__ bias) {
    int bid = blockIdx.x;
    int lvl = 0;
#pragma unroll
    for (int l = 1; l < 5; l++) if (bid >= c_cumB[l]) lvl = l;
    int S = c_S[lvl];
    int local = bid - c_cumB[lvl];
    int xt_count = S >> 3;
    int yt_count = S >> 1;
    int b = local / (xt_count * yt_count);
    int rem = local % (xt_count * yt_count);
    int y0 = (rem / xt_count) * 2;
    int xt = (rem % xt_count) * 8;
    const float* in = (lvl == 0) ? f2 : (lvl == 1) ? f3 : (lvl == 2) ? f4 : (lvl == 3) ? f5 : f6;

    int co = threadIdx.x;                        // 0..127 ; owns co and co+128
    __shared__ float4 s4buf[4 * 10 * 64];        // 40 KB
    float* sIn = (float*)s4buf;
    for (int idx = threadIdx.x; idx < 4 * 10 * 64; idx += 128) {
        int c4 = idx & 63;
        int xx = (idx >> 6) % 10;
        int r = idx / (10 * 64);
        int yy = y0 - 1 + r;
        int gx = xt - 1 + xx;
        float4 v = make_float4(0.f, 0.f, 0.f, 0.f);
        if (yy >= 0 && yy < S && gx >= 0 && gx < S)
            v = ((const float4*)(in + (((size_t)b * S + yy) * S + gx) * 256))[c4];
        s4buf[idx] = v;
    }
    __syncthreads();

    float acc0[16], acc1[16];
    float bv0 = bias[co];
    float bv1 = bias[co + 128];
#pragma unroll
    for (int p = 0; p < 16; p++) { acc0[p] = bv0; acc1[p] = bv1; }

    for (int kh = 0; kh < 3; kh++) {
        for (int kw = 0; kw < 3; kw++) {
            const float* wp = w + ((kh * 3 + kw) * 256) * 256 + co;
            for (int ci = 0; ci < 256; ci += 4) {
                float w00 = __ldg(wp + (ci + 0) * 256);
                float w01 = __ldg(wp + (ci + 1) * 256);
                float w02 = __ldg(wp + (ci + 2) * 256);
                float w03 = __ldg(wp + (ci + 3) * 256);
                float w10 = __ldg(wp + (ci + 0) * 256 + 128);
                float w11 = __ldg(wp + (ci + 1) * 256 + 128);
                float w12 = __ldg(wp + (ci + 2) * 256 + 128);
                float w13 = __ldg(wp + (ci + 3) * 256 + 128);
#pragma unroll
                for (int p = 0; p < 16; p++) {
                    int py = p >> 3, px = p & 7;
                    float4 sv = *(const float4*)&sIn[((py + kh) * 10 + (px + kw)) * 256 + ci];
                    acc0[p] = fmaf(sv.x, w00, acc0[p]);
                    acc0[p] = fmaf(sv.y, w01, acc0[p]);
                    acc0[p] = fmaf(sv.z, w02, acc0[p]);
                    acc0[p] = fmaf(sv.w, w03, acc0[p]);
                    acc1[p] = fmaf(sv.x, w10, acc1[p]);
                    acc1[p] = fmaf(sv.y, w11, acc1[p]);
                    acc1[p] = fmaf(sv.z, w12, acc1[p]);
                    acc1[p] = fmaf(sv.w, w13, acc1[p]);
                }
            }
        }
    }
#pragma unroll
    for (int p = 0; p < 16; p++) {
        int py = p >> 3, px = p & 7;
        size_t pixel = (size_t)c_Poff[lvl] + ((size_t)b * S + (y0 + py)) * S + (xt + px);
        g_hfeat[pixel * 256 + co] = fmaxf(acc0[p], 0.f);
        g_hfeat[pixel * 256 + co + 128] = fmaxf(acc1[p], 0.f);
    }
}

// ---------------- RPN 1x1 heads: 16 pixels/block, features staged once in smem ----------------
__global__ void rpn_head_kernel(const float* __restrict__ cw, const float* __restrict__ cb,
                                const float* __restrict__ bw, const float* __restrict__ bb) {
    __shared__ float sf[16 * 260];
    int p0 = blockIdx.x * 16;
    int tid = threadIdx.x;                       // 256

    for (int i = tid; i < 16 * 64; i += 256) {
        int row = i >> 6, c4 = i & 63;
        float4 v = ((const float4*)(g_hfeat + (size_t)(p0 + row) * 256))[c4];
        *(float4*)&sf[row * 260 + c4 * 4] = v;
    }
    __syncthreads();

    int p_local = tid >> 4;
    int o = tid & 15;
    if (o < 15) {
        float a;
        const float* wv;
        int st;
        if (o < 3) { a = cb[o]; wv = cw + o; st = 3; }
        else       { a = bb[o - 3]; wv = bw + (o - 3); st = 12; }
        const float* fp = sf + p_local * 260;
        for (int ci = 0; ci < 256; ci++) a += fp[ci] * __ldg(wv + ci * st);
        g_raw[(size_t)(p0 + p_local) * 16 + o] = a;
    }
}

// ---------------- RPN decode over all anchors ----------------
__global__ void rpn_decode_kernel(const float* __restrict__ info) {
    int t = blockIdx.x * blockDim.x + threadIdx.x;
    if (t >= 2 * 65472) return;
    int b = t / 65472;
    int r = t % 65472;
    int lvl = 0;
#pragma unroll
    for (int l = 1; l < 5; l++) if (r >= c_Aoff[l]) lvl = l;
    int local = r - c_Aoff[lvl];
    int hw = local / 3;
    int a = local % 3;
    int S = c_S[lvl];
    size_t p = (size_t)c_Poff[lvl] + (size_t)b * S * S + hw;

    const float* rp = g_raw + p * 16;
    float logit = rp[a];
    float d0 = rp[3 + a * 4 + 0], d1 = rp[3 + a * 4 + 1];
    float d2 = rp[3 + a * 4 + 2], d3 = rp[3 + a * 4 + 3];

    float score = 1.f / (1.f + expf(-logit));

    int stride = 4 << lvl;
    int iy = hw / S, ix = hw % S;
    const double AY[3] = {1.0, 1.4, 0.7};
    const double AX[3] = {1.0, 0.7, 1.4};
    double cyd = (iy + 0.5) * (double)stride;
    double cxd = (ix + 0.5) * (double)stride;
    double hd = 8.0 * (double)stride * AY[a];
    double wd = 8.0 * (double)stride * AX[a];
    float ay1 = (float)(cyd - hd / 2), ax1 = (float)(cxd - wd / 2);
    float ay2 = (float)(cyd + hd / 2), ax2 = (float)(cxd + wd / 2);

    float ah = ay2 - ay1, aw = ax2 - ax1;
    float acy = ay1 + 0.5f * ah, acx = ax1 + 0.5f * aw;

    float dh = fminf(d2, BBOX_CLIP), dw = fminf(d3, BBOX_CLIP);
    float ncy = d0 * ah + acy;
    float ncx = d1 * aw + acx;
    float nh = expf(dh) * ah;
    float nw = expf(dw) * aw;
    float y1 = ncy - 0.5f * nh, x1 = ncx - 0.5f * nw;
    float y2 = ncy + 0.5f * nh, x2 = ncx + 0.5f * nw;

    float ih = info[b * 5 + 0], iw = info[b * 5 + 1];
    y1 = fminf(fmaxf(y1, 0.f), ih);
    x1 = fminf(fmaxf(x1, 0.f), iw);
    y2 = fminf(fmaxf(y2, 0.f), ih);
    x2 = fminf(fmaxf(x2, 0.f), iw);

    int idx = b * 65472 + r;
    g_scores[idx] = score;
    g_boxes[idx * 4 + 0] = y1;
    g_boxes[idx * 4 + 1] = x1;
    g_boxes[idx * 4 + 2] = y2;
    g_boxes[idx * 4 + 3] = x2;
}

// ---------------- exact top-k via 64-bit radix select + bitonic sort ----------------
__global__ void topk_radix_kernel(int mode) {
    int tid = threadIdx.x;  // 1024
    const float* sc;
    const float* bxp;
    float* os;
    float* ob;
    int* oi;
    int n, k;
    if (mode == 0) {
        int b = blockIdx.x / 5, lvl = blockIdx.x % 5;
        sc = g_scores + b * 65472 + c_Aoff[lvl];
        bxp = g_boxes + (size_t)(b * 65472 + c_Aoff[lvl]) * 4;
        os = g_ts + (b * 5 + lvl) * 400;
        ob = g_tb + (size_t)(b * 5 + lvl) * 1600;
        oi = g_ti + (b * 5 + lvl) * 400;
        n = c_nl[lvl];
        k = c_kl[lvl];
    } else if (mode == 1) {
        int b = blockIdx.x;
        sc = g_cs + b * 640;
        bxp = g_cb + (size_t)b * 2560;
        os = g_dummy_s + b * 512;
        ob = g_rois + (size_t)b * 2048;
        oi = g_dummy_i + b * 512;
        n = 640; k = 512;
    } else {
        int b = blockIdx.x;
        sc = g_sc + b * 46080;
        bxp = g_bx + (size_t)b * 46080 * 4;
        os = g_dts + b * 500;
        ob = g_dtb + (size_t)b * 2000;
        oi = g_dti + b * 500;
        n = 46080; k = 500;
    }

    __shared__ unsigned int hist[256];
    __shared__ unsigned int suffix[256];
    __shared__ int s_krem, s_krem_next, s_chosen;
    __shared__ unsigned long long skeys[512];
    __shared__ int s_cnt;

    if (tid == 0) { s_krem = k; s_cnt = 0; }
    __syncthreads();

    unsigned long long pref = 0;
    for (int p = 7; p >= 0; p--) {
        if (tid < 256) hist[tid] = 0;
        __syncthreads();
        for (int j = tid; j < n; j += 1024) {
            unsigned long long key = (((unsigned long long)flip_f(sc[j])) << 32) | (unsigned int)(~(unsigned int)j);
            bool okc = (p == 7) || ((key >> (((unsigned)p + 1u) * 8u)) == pref);
            if (okc) atomicAdd(&hist[(unsigned)(key >> ((unsigned)p * 8u)) & 255u], 1u);
        }
        __syncthreads();
        if (tid < 256) suffix[tid] = hist[tid];
        __syncthreads();
        for (int d = 1; d < 256; d <<= 1) {
            unsigned v = 0;
            if (tid < 256) v = suffix[tid] + ((tid + d < 256) ? suffix[tid + d] : 0u);
            __syncthreads();
            if (tid < 256) suffix[tid] = v;
            __syncthreads();
        }
        if (tid < 256) {
            unsigned above = (tid == 255) ? 0u : suffix[tid + 1];
            if (suffix[tid] >= (unsigned)s_krem && above < (unsigned)s_krem) {
                s_chosen = tid;
                s_krem_next = s_krem - (int)above;
            }
        }
        __syncthreads();
        pref = (pref << 8) | (unsigned)s_chosen;
        if (tid == 0) s_krem = s_krem_next;
        __syncthreads();
    }
    unsigned long long kth = pref;

    for (int j = tid; j < n; j += 1024) {
        unsigned long long key = (((unsigned long long)flip_f(sc[j])) << 32) | (unsigned int)(~(unsigned int)j);
        if (key >= kth) skeys[atomicAdd(&s_cnt, 1)] = key;
    }
    __syncthreads();
    for (int idx = tid; idx < 512; idx += 1024)
        if (idx >= k) skeys[idx] = 0ull;
    __syncthreads();

    for (int size = 2; size <= 512; size <<= 1) {
        for (int stride = size >> 1; stride; stride >>= 1) {
            for (int idx = tid; idx < 512; idx += 1024) {
                int partner = idx ^ stride;
                if (partner > idx) {
                    bool dirDesc = ((idx & size) == 0);
                    unsigned long long a = skeys[idx], c2 = skeys[partner];
                    bool sw = dirDesc ? (a < c2) : (a > c2);
                    if (sw) { skeys[idx] = c2; skeys[partner] = a; }
                }
            }
            __syncthreads();
        }
    }

    for (int it = tid; it < k; it += 1024) {
        unsigned long long key = skeys[it];
        int j = (int)(~(unsigned int)(key & 0xFFFFFFFFull));
        os[it] = sc[j];
        oi[it] = j;
        ob[it * 4 + 0] = bxp[j * 4 + 0];
        ob[it * 4 + 1] = bxp[j * 4 + 1];
        ob[it * 4 + 2] = bxp[j * 4 + 2];
        ob[it * 4 + 3] = bxp[j * 4 + 3];
    }
}

// ---------------- batched RPN NMS (grid 10, 256 threads) ----------------
__global__ void nms_rpn_kernel() {
    int task = blockIdx.x;
    int b = task / 5, lvl = task % 5;
    int n = c_kl[lvl];
    int tid = threadIdx.x;  // 256
    __shared__ float sb[400 * 4];
    __shared__ float ss[400];
    __shared__ int sidx[128];
    __shared__ unsigned char sval[128];
    __shared__ float rv[8];
    __shared__ int ri[8];

    const float* tsg = g_ts + (b * 5 + lvl) * 400;
    const float* tbg = g_tb + (size_t)(b * 5 + lvl) * 1600;

    for (int j = tid; j < n; j += 256) {
        ss[j] = tsg[j];
        sb[j * 4 + 0] = tbg[j * 4 + 0];
        sb[j * 4 + 1] = tbg[j * 4 + 1];
        sb[j * 4 + 2] = tbg[j * 4 + 2];
        sb[j * 4 + 3] = tbg[j * 4 + 3];
    }
    __syncthreads();

    for (int it = 0; it < 128; it++) {
        float bv = NEG_INF;
        int bi = 0x7FFFFFFF;
        for (int j = tid; j < n; j += 256) {
            float v = ss[j];
            if (v > bv) { bv = v; bi = j; }
        }
#pragma unroll
        for (int o = 16; o; o >>= 1) {
            float ov = __shfl_down_sync(0xFFFFFFFFu, bv, o);
            int oidx = __shfl_down_sync(0xFFFFFFFFu, bi, o);
            if (ov > bv || (ov == bv && oidx < bi)) { bv = ov; bi = oidx; }
        }
        if ((tid & 31) == 0) { rv[tid >> 5] = bv; ri[tid >> 5] = bi; }
        __syncthreads();
        if (tid < 32) {
            bv = (tid < 8) ? rv[tid] : NEG_INF;
            bi = (tid < 8) ? ri[tid] : 0x7FFFFFFF;
#pragma unroll
            for (int o = 4; o; o >>= 1) {
                float ov = __shfl_down_sync(0xFFFFFFFFu, bv, o);
                int oidx = __shfl_down_sync(0xFFFFFFFFu, bi, o);
                if (ov > bv || (ov == bv && oidx < bi)) { bv = ov; bi = oidx; }
            }
            if (tid == 0) { rv[0] = bv; ri[0] = bi; }
        }
        __syncthreads();
        int j = ri[0];
        float vj = rv[0];
        if (tid == 0) { sidx[it] = j; sval[it] = (vj > VALID_THR) ? 1 : 0; }
        float jy1 = sb[j * 4 + 0], jx1 = sb[j * 4 + 1];
        float jy2 = sb[j * 4 + 2], jx2 = sb[j * 4 + 3];
        __syncthreads();
        for (int t = tid; t < n; t += 256) {
            float u = iou_f(jy1, jx1, jy2, jx2,
                            sb[t * 4 + 0], sb[t * 4 + 1], sb[t * 4 + 2], sb[t * 4 + 3]);
            if (u >= 0.7f) ss[t] = SUPPRESS;
        }
        __syncthreads();
    }

    for (int i = tid; i < 128; i += 256) {
        int j = sidx[i];
        bool ok = sval[i] != 0;
        int oidx = b * 640 + lvl * 128 + i;
        g_cs[oidx] = ok ? tsg[j] : SUPPRESS;
        g_cb[oidx * 4 + 0] = ok ? tbg[j * 4 + 0] : 0.f;
        g_cb[oidx * 4 + 1] = ok ? tbg[j * 4 + 1] : 0.f;
        g_cb[oidx * 4 + 2] = ok ? tbg[j * 4 + 2] : 0.f;
        g_cb[oidx * 4 + 3] = ok ? tbg[j * 4 + 3] : 0.f;
    }
}

// ---------------- multilevel ROI align (7x7, C=256), scalar ----------------
__global__ void roi_align_kernel(const float* __restrict__ f2, const float* __restrict__ f3,
                                 const float* __restrict__ f4, const float* __restrict__ f5,
                                 const float* __restrict__ f6) {
    int br = blockIdx.x;
    int b = br >> 9;
    int c = threadIdx.x;  // 256

    float y1 = g_rois[br * 4 + 0], x1 = g_rois[br * 4 + 1];
    float y2 = g_rois[br * 4 + 2], x2 = g_rois[br * 4 + 3];
    float h = y2 - y1, w = x2 - x1;
    float lvlf = floorf(log2f(sqrtf(fmaxf(h * w, 1e-8f)) / 224.0f + 1e-8f) + 4.0f);
    lvlf = fminf(fmaxf(lvlf, 2.0f), 6.0f);
    int li = (int)lvlf - 2;
    float stride = exp2f(lvlf);
    int S = 512 >> (li + 2);
    const float* f = (li == 0) ? f2 : (li == 1) ? f3 : (li == 2) ? f4 : (li == 3) ? f5 : f6;
    const float* fb = f + (size_t)b * S * S * 256;

    for (int iy = 0; iy < 7; iy++) {
        float ty = (iy + 0.5f) / 7.0f;
        float fy = (y1 + ty * h) / stride - 0.5f;
        float y0f = floorf(fy);
        float wy = fy - y0f;
        int yy0 = min(max((int)y0f, 0), S - 1);
        int yy1 = min(yy0 + 1, S - 1);
        for (int ix = 0; ix < 7; ix++) {
            float tx = (ix + 0.5f) / 7.0f;
            float fx = (x1 + tx * w) / stride - 0.5f;
            float x0f = floorf(fx);
            float wx = fx - x0f;
            int xx0 = min(max((int)x0f, 0), S - 1);
            int xx1 = min(xx0 + 1, S - 1);
            float v00 = fb[((size_t)yy0 * S + xx0) * 256 + c];
            float v01 = fb[((size_t)yy0 * S + xx1) * 256 + c];
            float v10 = fb[((size_t)yy1 * S + xx0) * 256 + c];
            float v11 = fb[((size_t)yy1 * S + xx1) * 256 + c];
            float v = v00 * (1 - wy) * (1 - wx) + v01 * (1 - wy) * wx +
                      v10 * wy * (1 - wx) + v11 * wy * wx;
            g_x[(size_t)br * 12544 + (iy * 7 + ix) * 256 + c] = v;
        }
    }
}

// ---------------- fp32 SGEMM 64x64 tile, BK=32, N=1024 (fc1 / fc2) ----------------
// coalesced scalar staging (k fastest); k-ascending FMA order -> bitwise same as BK=16.
__global__ void gemm_fc_kernel(int mode, const float* __restrict__ W,
                               const float* __restrict__ bias, int K) {
    const float* A = (mode == 0) ? g_x : g_h1;
    float* C = (mode == 0) ? g_h1 : g_h2;
    const int N = 1024;

    __shared__ float As[32 * 68];    // [k][row]
    __shared__ float Bs[32 * 64];    // [k][n]
    int tid = threadIdx.x;  // 256
    int tx = tid & 15, ty = tid >> 4;
    int m0 = blockIdx.y * 64, n0 = blockIdx.x * 64;

    float acc[4][4] = {};
    for (int k0 = 0; k0 < K; k0 += 32) {
#pragma unroll
        for (int l = 0; l < 8; l++) {            // A: 64 rows x 32 k
            int e = tid + 256 * l;
            int r = e >> 5, cc = e & 31;         // k fastest -> coalesced
            As[cc * 68 + r] = A[(size_t)(m0 + r) * K + k0 + cc];
        }
#pragma unroll
        for (int l = 0; l < 8; l++) {            // B: 32 k x 64 n
            int e = tid + 256 * l;
            int r = e >> 6, cc = e & 63;         // n fastest -> coalesced
            Bs[r * 64 + cc] = W[(size_t)(k0 + r) * N + n0 + cc];
        }
        __syncthreads();
#pragma unroll
        for (int k = 0; k < 32; k++) {
            float4 av = *(const float4*)&As[k * 68 + ty * 4];
            float4 bv = *(const float4*)&Bs[k * 64 + tx * 4];
            float a[4] = {av.x, av.y, av.z, av.w};
            float bq[4] = {bv.x, bv.y, bv.z, bv.w};
#pragma unroll
            for (int i = 0; i < 4; i++)
#pragma unroll
                for (int j = 0; j < 4; j++) acc[i][j] += a[i] * bq[j];
        }
        __syncthreads();
    }
#pragma unroll
    for (int i = 0; i < 4; i++) {
        int m = m0 + ty * 4 + i;
#pragma unroll
        for (int j = 0; j < 4; j++) {
            int n = n0 + tx * 4 + j;
            C[(size_t)m * N + n] = fmaxf(acc[i][j] + bias[n], 0.f);
        }
    }
}

// ---------------- fp32 tiled SGEMM 64x64, bounds-checked (cls / boxr) ----------------
__global__ void gemm_kernel(int mode, const float* __restrict__ W, const float* __restrict__ bias,
                            int K, int N, int do_relu) {
    const float* A = g_h2;
    float* C = (mode == 2) ? g_cls : g_boxr;

    __shared__ float4 As4[16 * 17];   // As[16][68]
    __shared__ float4 Bs4[16 * 16];   // Bs[16][64]
    float* As = (float*)As4;
    float* Bs = (float*)Bs4;
    int tid = threadIdx.x;  // 256
    int tx = tid & 15, ty = tid >> 4;
    int m0 = blockIdx.y * 64, n0 = blockIdx.x * 64;

    float acc[4][4] = {};
    for (int k0 = 0; k0 < K; k0 += 16) {
#pragma unroll
        for (int l = 0; l < 4; l++) {
            int e = tid + 256 * l;
            int r = e >> 4, cc = e & 15;
            As[cc * 68 + r] = A[(size_t)(m0 + r) * K + k0 + cc];
        }
#pragma unroll
        for (int l = 0; l < 4; l++) {
            int e = tid + 256 * l;
            int r = e >> 6, cc = e & 63;
            Bs[r * 64 + cc] = (n0 + cc < N) ? W[(size_t)(k0 + r) * N + n0 + cc] : 0.f;
        }
        __syncthreads();
#pragma unroll
        for (int k = 0; k < 16; k++) {
            float4 av = *(const float4*)&As[k * 68 + ty * 4];
            float4 bv = *(const float4*)&Bs[k * 64 + tx * 4];
            float a[4] = {av.x, av.y, av.z, av.w};
            float bq[4] = {bv.x, bv.y, bv.z, bv.w};
#pragma unroll
            for (int i = 0; i < 4; i++)
#pragma unroll
                for (int j = 0; j < 4; j++) acc[i][j] += a[i] * bq[j];
        }
        __syncthreads();
    }
#pragma unroll
    for (int i = 0; i < 4; i++) {
        int m = m0 + ty * 4 + i;
#pragma unroll
        for (int j = 0; j < 4; j++) {
            int n = n0 + tx * 4 + j;
            if (n < N) {
                float v = acc[i][j] + bias[n];
                if (do_relu) v = fmaxf(v, 0.f);
                C[(size_t)m * N + n] = v;
            }
        }
    }
}

// ---------------- softmax over 91 classes + per-class box decode + clip ----------------
__global__ void softmax_decode_kernel(const float* __restrict__ info) {
    int br = blockIdx.x;
    int b = br >> 9;
    int r = br & 511;
    int tid = threadIdx.x;  // 96

    __shared__ float sl[91];
    __shared__ float smax, ssum;
    const float* lg = g_cls + (size_t)br * 91;
    if (tid < 91) sl[tid] = lg[tid];
    __syncthreads();
    if (tid == 0) {
        float m = sl[0];
        for (int i = 1; i < 91; i++) m = fmaxf(m, sl[i]);
        float s = 0.f;
        for (int i = 0; i < 91; i++) s += expf(sl[i] - m);
        smax = m;
        ssum = s;
    }
    __syncthreads();

    float ry1 = g_rois[br * 4 + 0], rx1 = g_rois[br * 4 + 1];
    float ry2 = g_rois[br * 4 + 2], rx2 = g_rois[br * 4 + 3];
    float ah = ry2 - ry1, aw = rx2 - rx1;
    float acy = ry1 + 0.5f * ah, acx = rx1 + 0.5f * aw;
    float ih = info[b * 5 + 0], iw = info[b * 5 + 1];

    if (tid < 90) {
        int j = tid + 1;
        float p = expf(sl[j] - smax) / ssum;
        const float* dl = g_boxr + (size_t)br * 364 + j * 4;
        float dy = dl[0] / 10.f, dx = dl[1] / 10.f;
        float dh = fminf(dl[2] / 5.f, BBOX_CLIP), dw = fminf(dl[3] / 5.f, BBOX_CLIP);
        float cy = dy * ah + acy, cx = dx * aw + acx;
        float hh = expf(dh) * ah, ww = expf(dw) * aw;
        float by1 = cy - 0.5f * hh, bx1 = cx - 0.5f * ww;
        float by2 = cy + 0.5f * hh, bx2 = cx + 0.5f * ww;
        by1 = fminf(fmaxf(by1, 0.f), ih);
        bx1 = fminf(fmaxf(bx1, 0.f), iw);
        by2 = fminf(fmaxf(by2, 0.f), ih);
        bx2 = fminf(fmaxf(bx2, 0.f), iw);
        int oi = r * 90 + tid;
        g_sc[b * 46080 + oi] = p;
        size_t bo = ((size_t)b * 46080 + oi) * 4;
        g_bx[bo + 0] = by1;
        g_bx[bo + 1] = bx1;
        g_bx[bo + 2] = by2;
        g_bx[bo + 3] = bx2;
    }
}

// ---------------- detection NMS (grid 2, 256 threads) + output ----------------
__global__ void nms_det_kernel(float* __restrict__ out) {
    int b = blockIdx.x;
    int tid = threadIdx.x;  // 256
    __shared__ float ob[500 * 4];
    __shared__ float ss[500];
    __shared__ float scls[500];
    __shared__ int sidx[100];
    __shared__ unsigned char sval[100];
    __shared__ float rv[8];
    __shared__ int ri[8];
    __shared__ int cnt;

    for (int j = tid; j < 500; j += 256) {
        float cls = (float)(g_dti[b * 500 + j] % 90 + 1);
        scls[j] = cls;
        ss[j] = g_dts[b * 500 + j];
        float off = cls * 1024.f;
        ob[j * 4 + 0] = g_dtb[(b * 500 + j) * 4 + 0] + off;
        ob[j * 4 + 1] = g_dtb[(b * 500 + j) * 4 + 1] + off;
        ob[j * 4 + 2] = g_dtb[(b * 500 + j) * 4 + 2] + off;
        ob[j * 4 + 3] = g_dtb[(b * 500 + j) * 4 + 3] + off;
    }
    if (tid == 0) cnt = 0;
    __syncthreads();

    for (int it = 0; it < 100; it++) {
        float bv = NEG_INF;
        int bi = 0x7FFFFFFF;
        for (int j = tid; j < 500; j += 256) {
            float v = ss[j];
            if (v > bv) { bv = v; bi = j; }
        }
#pragma unroll
        for (int o = 16; o; o >>= 1) {
            float ov = __shfl_down_sync(0xFFFFFFFFu, bv, o);
            int oidx = __shfl_down_sync(0xFFFFFFFFu, bi, o);
            if (ov > bv || (ov == bv && oidx < bi)) { bv = ov; bi = oidx; }
        }
        if ((tid & 31) == 0) { rv[tid >> 5] = bv; ri[tid >> 5] = bi; }
        __syncthreads();
        if (tid < 32) {
            bv = (tid < 8) ? rv[tid] : NEG_INF;
            bi = (tid < 8) ? ri[tid] : 0x7FFFFFFF;
#pragma unroll
            for (int o = 4; o; o >>= 1) {
                float ov = __shfl_down_sync(0xFFFFFFFFu, bv, o);
                int oidx = __shfl_down_sync(0xFFFFFFFFu, bi, o);
                if (ov > bv || (ov == bv && oidx < bi)) { bv = ov; bi = oidx; }
            }
            if (tid == 0) { rv[0] = bv; ri[0] = bi; }
        }
        __syncthreads();
        int j = ri[0];
        float vj = rv[0];
        if (tid == 0) { sidx[it] = j; sval[it] = (vj > VALID_THR) ? 1 : 0; }
        float jy1 = ob[j * 4 + 0], jx1 = ob[j * 4 + 1];
        float jy2 = ob[j * 4 + 2], jx2 = ob[j * 4 + 3];
        __syncthreads();
        for (int t = tid; t < 500; t += 256) {
            float u = iou_f(jy1, jx1, jy2, jx2,
                            ob[t * 4 + 0], ob[t * 4 + 1], ob[t * 4 + 2], ob[t * 4 + 3]);
            if (u >= 0.5f) ss[t] = SUPPRESS;
        }
        __syncthreads();
    }

    for (int i = tid; i < 100; i += 256) {
        int j = sidx[i];
        bool ok = sval[i] != 0;
        for (int d = 0; d < 4; d++)
            out[2 + (b * 100 + i) * 4 + d] = ok ? g_dtb[(b * 500 + j) * 4 + d] : 0.f;
        out[802 + b * 100 + i] = ok ? scls[j] : 0.f;
        out[1002 + b * 100 + i] = ok ? g_dts[b * 500 + j] : 0.f;
        if (ok) atomicAdd(&cnt, 1);
    }
    __syncthreads();
    if (tid == 0) out[b] = (float)cnt;
}

// ---------------- host launch ----------------
extern "C" void kernel_launch(void* const* d_in, const int* in_sizes, int n_in,
                              void* d_out, int out_size) {
    const float* fpn[5] = {(const float*)d_in[0], (const float*)d_in[1], (const float*)d_in[2],
                           (const float*)d_in[3], (const float*)d_in[4]};
    const float* info = (const float*)d_in[5];
    const float* rpn_conv_w = (const float*)d_in[6];
    const float* rpn_conv_b = (const float*)d_in[7];
    const float* rpn_cls_w = (const float*)d_in[8];
    const float* rpn_cls_b = (const float*)d_in[9];
    const float* rpn_box_w = (const float*)d_in[10];
    const float* rpn_box_b = (const float*)d_in[11];
    const float* fc1_w = (const float*)d_in[12];
    const float* fc1_b = (const float*)d_in[13];
    const float* fc2_w = (const float*)d_in[14];
    const float* fc2_b = (const float*)d_in[15];
    const float* cls_w = (const float*)d_in[16];
    const float* cls_b = (const float*)d_in[17];
    const float* boxr_w = (const float*)d_in[18];
    const float* boxr_b = (const float*)d_in[19];
    float* out = (float*)d_out;

    conv3x3_relu_kernel<<<2728, 128>>>(fpn[0], fpn[1], fpn[2], fpn[3], fpn[4],
                                       rpn_conv_w, rpn_conv_b);
    rpn_head_kernel<<<2728, 256>>>(rpn_cls_w, rpn_cls_b, rpn_box_w, rpn_box_b);
    rpn_decode_kernel<<<(2 * 65472 + 255) / 256, 256>>>(info);

    topk_radix_kernel<<<10, 1024>>>(0);
    nms_rpn_kernel<<<10, 256>>>();
    topk_radix_kernel<<<2, 1024>>>(1);

    roi_align_kernel<<<1024, 256>>>(fpn[0], fpn[1], fpn[2], fpn[3], fpn[4]);

    gemm_fc_kernel<<<dim3(16, 16), 256>>>(0, fc1_w, fc1_b, 12544);
    gemm_fc_kernel<<<dim3(16, 16), 256>>>(1, fc2_w, fc2_b, 1024);
    gemm_kernel<<<dim3(2, 16), 256>>>(2, cls_w, cls_b, 1024, 91, 0);
    gemm_kernel<<<dim3(6, 16), 256>>>(3, boxr_w, boxr_b, 1024, 364, 0);

    softmax_decode_kernel<<<1024, 96>>>(info);

    topk_radix_kernel<<<2, 1024>>>(2);
    nms_det_kernel<<<2, 256>>>(out);
}